// round 7
// baseline (speedup 1.0000x reference)
#include <cuda_runtime.h>
#include <cuda_bf16.h>
#include <mma.h>
#include <cstdint>

using namespace nvcuda;

#define NPIX 8192
#define NPTS 8192
#define NTOK 16384
#define NWIN 128
#define CAP  256
#define NCHUNK 32

// ---------------- scratch (device globals; no allocation) ----------------
__device__ __nv_bfloat16 g_imgh[2097152], g_imgl[2097152];   // NCHW image, split
__device__ __nv_bfloat16 g_feath[NTOK * 128], g_featl[NTOK * 128];
__device__ float g_qkv [NTOK * 384];
__device__ __nv_bfloat16 g_oh[NPIX * 128], g_ol[NPIX * 128];
__device__ __nv_bfloat16 g_resh[NPIX * 128], g_resl[NPIX * 128];
__device__ __nv_bfloat16 g_wh[147456];
__device__ __nv_bfloat16 g_wl[147456];
__device__ int   g_ptw [NPTS];
__device__ int   g_hist[NCHUNK * NWIN];
__device__ int   g_win_tok[NWIN * CAP];
__device__ int   g_win_cnt[NWIN];

#define WOFF_CI  0
#define WOFF_QKV 32768
#define WOFF_PR  81920
#define WOFF_ODE 98304
#define WOFF_CO  114688

// ---------------- helpers ----------------
__device__ __forceinline__ uint32_t bf16x2_of(float hi, float lo) {
    uint32_t r; asm("cvt.rn.bf16x2.f32 %0, %1, %2;" : "=r"(r) : "f"(hi), "f"(lo)); return r;
}
__device__ __forceinline__ float bf16lo_f(uint32_t v) { return __uint_as_float(v << 16); }
__device__ __forceinline__ float bf16hi_f(uint32_t v) { return __uint_as_float(v & 0xffff0000u); }

__device__ __forceinline__ uint32_t smem_u32(const void* p) {
    uint32_t a;
    asm("{ .reg .u64 t; cvta.to.shared.u64 t, %1; cvt.u32.u64 %0, t; }" : "=r"(a) : "l"(p));
    return a;
}
__device__ __forceinline__ void cpa16(uint32_t s, const void* g) {
    asm volatile("cp.async.cg.shared.global [%0], [%1], 16;" :: "r"(s), "l"(g));
}
__device__ __forceinline__ void cp_commit() { asm volatile("cp.async.commit_group;" ::: "memory"); }
__device__ __forceinline__ void cp_wait1() { asm volatile("cp.async.wait_group 1;" ::: "memory"); }
__device__ __forceinline__ void cp_wait0() { asm volatile("cp.async.wait_group 0;" ::: "memory"); }

// ============================================================================
// Merged prep: weight split | points split | wid+hist+pixel slots | image split
//   blocks [0,576): weights; [576,1600): pts; [1600,1632): hist; [1632,3680): img
// ============================================================================
__global__ void prep(const float* __restrict__ wci, const float* __restrict__ wqkv,
                     const float* __restrict__ wpr, const float* __restrict__ wode,
                     const float* __restrict__ wco, const float* __restrict__ ptsf,
                     const int* __restrict__ uv, const float* __restrict__ img) {
    __shared__ int cnt[NWIN];
    int bid = blockIdx.x, t = threadIdx.x;
    if (bid < 576) {
        int i = bid * 256 + t;
        if (i >= 147456) return;
        float x;
        if (i < WOFF_QKV)      x = wci [i];
        else if (i < WOFF_PR)  x = wqkv[i - WOFF_QKV];
        else if (i < WOFF_ODE) x = wpr [i - WOFF_PR];
        else if (i < WOFF_CO)  x = wode[i - WOFF_ODE];
        else                   x = wco [i - WOFF_CO];
        __nv_bfloat16 h = __float2bfloat16(x);
        g_wh[i] = h;
        g_wl[i] = __float2bfloat16(x - __bfloat162float(h));
    } else if (bid < 1600) {
        int i = (bid - 576) * 256 + t;   // over 262144 float4
        float4 v = ((const float4*)ptsf)[i];
        uint32_t h0 = bf16x2_of(v.y, v.x);
        uint32_t h1 = bf16x2_of(v.w, v.z);
        uint32_t l0 = bf16x2_of(v.y - bf16hi_f(h0), v.x - bf16lo_f(h0));
        uint32_t l1 = bf16x2_of(v.w - bf16hi_f(h1), v.z - bf16lo_f(h1));
        uint32_t* fh = (uint32_t*)g_feath;
        uint32_t* fl = (uint32_t*)g_featl;
        int o = 524288 + 2 * i;
        fh[o] = h0; fh[o + 1] = h1;
        fl[o] = l0; fl[o + 1] = l1;
    } else if (bid < 1632) {
        int c = bid - 1600;
        int i = c * 256 + t;
        if (t < NWIN) cnt[t] = 0;
        __syncthreads();
        int b = uv[3 * i] & 1;
        int u = uv[3 * i + 1] & 63;
        int v = uv[3 * i + 2] & 63;
        int wid = ((b * 8 + (v >> 3)) << 3) + (u >> 3);
        g_ptw[i] = wid;
        atomicAdd(&cnt[wid], 1);
        {
            int w = i >> 6, r = i & 63;
            int wb = w >> 6, wy = (w >> 3) & 7, wx = w & 7;
            int pv = wy * 8 + (r >> 3), pu = wx * 8 + (r & 7);
            g_win_tok[w * CAP + r] = wb * 4096 + pv * 64 + pu;
        }
        __syncthreads();
        if (t < NWIN) g_hist[c * NWIN + t] = cnt[t];
    } else {
        int i = (bid - 1632) * 256 + t;  // over 524288 float4 of image
        float4 v = ((const float4*)img)[i];
        uint32_t h0 = bf16x2_of(v.y, v.x);
        uint32_t h1 = bf16x2_of(v.w, v.z);
        uint32_t l0 = bf16x2_of(v.y - bf16hi_f(h0), v.x - bf16lo_f(h0));
        uint32_t l1 = bf16x2_of(v.w - bf16hi_f(h1), v.z - bf16lo_f(h1));
        uint32_t* ih = (uint32_t*)g_imgh;
        uint32_t* il = (uint32_t*)g_imgl;
        int o = 2 * i;
        ih[o] = h0; ih[o + 1] = h1;
        il[o] = l0; il[o + 1] = l1;
    }
}

// ---------------- scatter with inline cross-chunk scan ----------------
__global__ void pt_scatter() {
    __shared__ int cnt[NWIN];
    int t = threadIdx.x;
    int lane = t & 31;
    int c = blockIdx.x;
    int i = c * 256 + t;
    if (t < NWIN) {
        int run = 0;
        for (int cc = 0; cc < c; cc++) run += g_hist[cc * NWIN + t];
        cnt[t] = run;
        if (c == NCHUNK - 1) {
            int tot = 64 + run + g_hist[(NCHUNK - 1) * NWIN + t];
            g_win_cnt[t] = tot < CAP ? tot : CAP;
        }
    }
    __syncthreads();
    int wid = g_ptw[i];
    for (int wv = 0; wv < 8; wv++) {
        if ((t >> 5) == wv) {
            unsigned mask = __match_any_sync(0xffffffffu, wid);
            int prior = __popc(mask & ((1u << lane) - 1u));
            int base = cnt[wid];
            __syncwarp();
            int rank = 64 + base + prior;
            if (rank < CAP) g_win_tok[wid * CAP + rank] = NPIX + i;
            if (prior == 0) cnt[wid] = base + __popc(mask);
        }
        __syncthreads();
    }
}

// ============================================================================
// Wide pipelined bf16 GEMM core: block 128M x 128N, 8 warps (4M x 2N),
// warp tile 32M x 64N, hi/lo 3-pass. K-step 32, double-buffered cp.async.
// smem/stage: sAh|sAl (10240 ea, pitch 40) sBh|sBl (10240 ea). 2 stages = 81920.
// scratch (epilogue) aliases the buffers.
// ============================================================================
#define WIDE_SMEM 81920

#define WIDE_MAINLOOP(A_FRAG_LOADS)                                                  \
    wmma::fragment<wmma::accumulator, 16, 16, 16, float> acc[2][4];                  \
    _Pragma("unroll")                                                                \
    for (int mi = 0; mi < 2; mi++)                                                   \
        _Pragma("unroll")                                                            \
        for (int ni = 0; ni < 4; ni++)                                               \
            wmma::fill_fragment(acc[mi][ni], 0.f);                                   \
    issue(0, 0);                                                                     \
    for (int kt = 0; kt < KT; kt++) {                                                \
        int sb = (kt & 1) * 40960;                                                   \
        if (kt + 1 < KT) { issue(kt + 1, ((kt + 1) & 1) * 40960); cp_wait1(); }      \
        else cp_wait0();                                                             \
        __syncthreads();                                                             \
        _Pragma("unroll")                                                            \
        for (int ks = 0; ks < 2; ks++) {                                             \
            A_FRAG_LOADS                                                             \
            _Pragma("unroll")                                                        \
            for (int ni = 0; ni < 4; ni++) {                                         \
                wmma::fragment<wmma::matrix_b, 16, 16, 16, __nv_bfloat16, wmma::col_major> bh, bl; \
                wmma::load_matrix_sync(bh, (__nv_bfloat16*)(sm + sb + 20480) + (size_t)(n0 + ni * 16) * 40 + ks * 16, 40); \
                wmma::load_matrix_sync(bl, (__nv_bfloat16*)(sm + sb + 30720) + (size_t)(n0 + ni * 16) * 40 + ks * 16, 40); \
                wmma::mma_sync(acc[0][ni], ah0, bh, acc[0][ni]);                     \
                wmma::mma_sync(acc[1][ni], ah1, bh, acc[1][ni]);                     \
                wmma::mma_sync(acc[0][ni], al0, bh, acc[0][ni]);                     \
                wmma::mma_sync(acc[1][ni], al1, bh, acc[1][ni]);                     \
                wmma::mma_sync(acc[0][ni], ah0, bl, acc[0][ni]);                     \
                wmma::mma_sync(acc[1][ni], ah1, bl, acc[1][ni]);                     \
            }                                                                        \
        }                                                                            \
        __syncthreads();                                                             \
    }

#define A_LOADS_ROW                                                                  \
    wmma::fragment<wmma::matrix_a, 16, 16, 16, __nv_bfloat16, wmma::row_major> ah0, ah1, al0, al1; \
    wmma::load_matrix_sync(ah0, (__nv_bfloat16*)(sm + sb)         + (size_t)m0 * 40 + ks * 16, 40); \
    wmma::load_matrix_sync(ah1, (__nv_bfloat16*)(sm + sb)         + (size_t)(m0 + 16) * 40 + ks * 16, 40); \
    wmma::load_matrix_sync(al0, (__nv_bfloat16*)(sm + sb + 10240) + (size_t)m0 * 40 + ks * 16, 40); \
    wmma::load_matrix_sync(al1, (__nv_bfloat16*)(sm + sb + 10240) + (size_t)(m0 + 16) * 40 + ks * 16, 40);

// ---- generic wide GEMM: C fp32 [M][ldc] at col0, with optional Q-skip ----
__global__ __launch_bounds__(256) void wgemm(const __nv_bfloat16* __restrict__ Ah,
                                             const __nv_bfloat16* __restrict__ Al,
                                             const __nv_bfloat16* __restrict__ Bh,
                                             const __nv_bfloat16* __restrict__ Bl,
                                             const float* __restrict__ bias,
                                             float* __restrict__ C, int ldc, int K,
                                             int qcolsplit, int qrowblk) {
    extern __shared__ __align__(16) char sm[];
    const int col0 = blockIdx.x << 7;
    if (col0 < qcolsplit && (int)blockIdx.y >= qrowblk) return;
    const uint32_t smb = smem_u32(sm);
    const int t = threadIdx.x;
    const int w = t >> 5;
    const int row0 = blockIdx.y << 7;
    const int m0 = (w >> 1) << 5, n0 = (w & 1) << 6;
    const int KT = K >> 5;

    auto issue = [&](int kt, int sb) {
        int k0 = kt << 5;
#pragma unroll
        for (int i = 0; i < 2; i++) {
            int id = t + (i << 8);
            int r = id >> 2, k8 = (id & 3) << 3;
            uint32_t so = (uint32_t)(r * 40 + k8) << 1;
            cpa16(smb + sb + so,         Ah + (size_t)(row0 + r) * K + k0 + k8);
            cpa16(smb + sb + 10240 + so, Al + (size_t)(row0 + r) * K + k0 + k8);
            cpa16(smb + sb + 20480 + so, Bh + (size_t)(col0 + r) * K + k0 + k8);
            cpa16(smb + sb + 30720 + so, Bl + (size_t)(col0 + r) * K + k0 + k8);
        }
        cp_commit();
    };

    WIDE_MAINLOOP(A_LOADS_ROW)

    float* scratch = (float*)sm;
#pragma unroll
    for (int mi = 0; mi < 2; mi++)
#pragma unroll
        for (int ni = 0; ni < 4; ni++)
            wmma::store_matrix_sync(scratch + (size_t)(m0 + mi * 16) * 128 + n0 + ni * 16,
                                    acc[mi][ni], 128, wmma::mem_row_major);
    __syncthreads();

    int r = t >> 1, cc = (t & 1) << 6;
#pragma unroll
    for (int q = 0; q < 16; q++) {
        float4 v = *(float4*)(scratch + r * 128 + cc + q * 4);
        float4 bb = *(const float4*)(bias + col0 + cc + q * 4);
        v.x += bb.x; v.y += bb.y; v.z += bb.z; v.w += bb.w;
        *(float4*)(C + (size_t)(row0 + r) * ldc + col0 + cc + q * 4) = v;
    }
}

// ---- conv_in: A col-major from c-major split image; out bf16 h/l feat ----
// smem/stage: sAh|sAl (8704 ea, [32][136]) sBh|sBl (10240 ea) = 37888; x2 = 75776
#define CA_SMEM 75776

__global__ __launch_bounds__(256) void wgemm_ca(const __nv_bfloat16* __restrict__ Ah,
                                                const __nv_bfloat16* __restrict__ Al,
                                                const __nv_bfloat16* __restrict__ Bh,
                                                const __nv_bfloat16* __restrict__ Bl,
                                                const float* __restrict__ bias,
                                                __nv_bfloat16* __restrict__ Ch,
                                                __nv_bfloat16* __restrict__ Cl, int K) {
    extern __shared__ __align__(16) char sm[];
    const uint32_t smb = smem_u32(sm);
    const int t = threadIdx.x;
    const int w = t >> 5;
    const int row0 = blockIdx.y << 7;            // pixel row
    const int b = row0 >> 12, hw0 = row0 & 4095;
    const int col0 = 0;
    const int m0 = (w >> 1) << 5, n0 = (w & 1) << 6;
    const int KT = K >> 5;

    auto issue = [&](int kt, int stg) {
        int k0 = kt << 5;
        int sb = stg * 37888;
#pragma unroll
        for (int i = 0; i < 2; i++) {
            int id = t + (i << 8);
            int kk = id >> 4, m8 = (id & 15) << 3;
            uint32_t so = (uint32_t)(kk * 136 + m8) << 1;
            const size_t g = (size_t)b * 1048576 + (size_t)(k0 + kk) * 4096 + hw0 + m8;
            cpa16(smb + sb + so,        Ah + g);
            cpa16(smb + sb + 8704 + so, Al + g);
        }
#pragma unroll
        for (int i = 0; i < 2; i++) {
            int id = t + (i << 8);
            int r = id >> 2, k8 = (id & 3) << 3;
            uint32_t so = (uint32_t)(r * 40 + k8) << 1;
            cpa16(smb + sb + 17408 + so, Bh + (size_t)r * K + k0 + k8);
            cpa16(smb + sb + 27648 + so, Bl + (size_t)r * K + k0 + k8);
        }
        cp_commit();
    };

    wmma::fragment<wmma::accumulator, 16, 16, 16, float> acc[2][4];
#pragma unroll
    for (int mi = 0; mi < 2; mi++)
#pragma unroll
        for (int ni = 0; ni < 4; ni++)
            wmma::fill_fragment(acc[mi][ni], 0.f);

    issue(0, 0);
    for (int kt = 0; kt < KT; kt++) {
        int sb = (kt & 1) * 37888;
        if (kt + 1 < KT) { issue(kt + 1, (kt + 1) & 1); cp_wait1(); }
        else cp_wait0();
        __syncthreads();
#pragma unroll
        for (int ks = 0; ks < 2; ks++) {
            wmma::fragment<wmma::matrix_a, 16, 16, 16, __nv_bfloat16, wmma::col_major> ah0, ah1, al0, al1;
            wmma::load_matrix_sync(ah0, (__nv_bfloat16*)(sm + sb)        + (size_t)ks * 16 * 136 + m0, 136);
            wmma::load_matrix_sync(ah1, (__nv_bfloat16*)(sm + sb)        + (size_t)ks * 16 * 136 + m0 + 16, 136);
            wmma::load_matrix_sync(al0, (__nv_bfloat16*)(sm + sb + 8704) + (size_t)ks * 16 * 136 + m0, 136);
            wmma::load_matrix_sync(al1, (__nv_bfloat16*)(sm + sb + 8704) + (size_t)ks * 16 * 136 + m0 + 16, 136);
#pragma unroll
            for (int ni = 0; ni < 4; ni++) {
                wmma::fragment<wmma::matrix_b, 16, 16, 16, __nv_bfloat16, wmma::col_major> bh, bl;
                wmma::load_matrix_sync(bh, (__nv_bfloat16*)(sm + sb + 17408) + (size_t)(n0 + ni * 16) * 40 + ks * 16, 40);
                wmma::load_matrix_sync(bl, (__nv_bfloat16*)(sm + sb + 27648) + (size_t)(n0 + ni * 16) * 40 + ks * 16, 40);
                wmma::mma_sync(acc[0][ni], ah0, bh, acc[0][ni]);
                wmma::mma_sync(acc[1][ni], ah1, bh, acc[1][ni]);
                wmma::mma_sync(acc[0][ni], al0, bh, acc[0][ni]);
                wmma::mma_sync(acc[1][ni], al1, bh, acc[1][ni]);
                wmma::mma_sync(acc[0][ni], ah0, bl, acc[0][ni]);
                wmma::mma_sync(acc[1][ni], ah1, bl, acc[1][ni]);
            }
        }
        __syncthreads();
    }

    float* scratch = (float*)sm;
#pragma unroll
    for (int mi = 0; mi < 2; mi++)
#pragma unroll
        for (int ni = 0; ni < 4; ni++)
            wmma::store_matrix_sync(scratch + (size_t)(m0 + mi * 16) * 128 + n0 + ni * 16,
                                    acc[mi][ni], 128, wmma::mem_row_major);
    __syncthreads();

    int r = t >> 1, cc = (t & 1) << 6;
    uint32_t* ch32 = (uint32_t*)Ch;
    uint32_t* cl32 = (uint32_t*)Cl;
#pragma unroll
    for (int q = 0; q < 16; q++) {
        float4 v = *(float4*)(scratch + r * 128 + cc + q * 4);
        float4 bb = *(const float4*)(bias + col0 + cc + q * 4);
        v.x += bb.x; v.y += bb.y; v.z += bb.z; v.w += bb.w;
        uint32_t h01 = bf16x2_of(v.y, v.x);
        uint32_t h23 = bf16x2_of(v.w, v.z);
        uint32_t l01 = bf16x2_of(v.y - bf16hi_f(h01), v.x - bf16lo_f(h01));
        uint32_t l23 = bf16x2_of(v.w - bf16hi_f(h23), v.z - bf16lo_f(h23));
        int o = (row0 + r) * 64 + ((cc) >> 1) + q * 2;
        ch32[o] = h01; ch32[o + 1] = h23;
        cl32[o] = l01; cl32[o + 1] = l23;
    }
}

// ---- conv_out: wide GEMM with transposed NCHW store ----
__global__ __launch_bounds__(256) void wgemm_tr(const __nv_bfloat16* __restrict__ Ah,
                                                const __nv_bfloat16* __restrict__ Al,
                                                const __nv_bfloat16* __restrict__ Bh,
                                                const __nv_bfloat16* __restrict__ Bl,
                                                const float* __restrict__ bias,
                                                float* __restrict__ out, int K) {
    extern __shared__ __align__(16) char sm[];
    const uint32_t smb = smem_u32(sm);
    const int t = threadIdx.x;
    const int w = t >> 5;
    const int row0 = blockIdx.y << 7, col0 = blockIdx.x << 7;
    const int b2 = row0 >> 12, hw0 = row0 & 4095;
    const int m0 = (w >> 1) << 5, n0 = (w & 1) << 6;
    const int KT = K >> 5;

    auto issue = [&](int kt, int sb) {
        int k0 = kt << 5;
#pragma unroll
        for (int i = 0; i < 2; i++) {
            int id = t + (i << 8);
            int r = id >> 2, k8 = (id & 3) << 3;
            uint32_t so = (uint32_t)(r * 40 + k8) << 1;
            cpa16(smb + sb + so,         Ah + (size_t)(row0 + r) * K + k0 + k8);
            cpa16(smb + sb + 10240 + so, Al + (size_t)(row0 + r) * K + k0 + k8);
            cpa16(smb + sb + 20480 + so, Bh + (size_t)(col0 + r) * K + k0 + k8);
            cpa16(smb + sb + 30720 + so, Bl + (size_t)(col0 + r) * K + k0 + k8);
        }
        cp_commit();
    };

    WIDE_MAINLOOP(A_LOADS_ROW)

    // store col-major: scratch[n][m] pitch 132
    float* scratch = (float*)sm;
#pragma unroll
    for (int mi = 0; mi < 2; mi++)
#pragma unroll
        for (int ni = 0; ni < 4; ni++)
            wmma::store_matrix_sync(scratch + (size_t)(n0 + ni * 16) * 132 + m0 + mi * 16,
                                    acc[mi][ni], 132, wmma::mem_col_major);
    __syncthreads();

    const int lane = t & 31;
#pragma unroll
    for (int nn = 0; nn < 16; nn++) {
        int n = (w << 4) + nn;
        float bv = bias[col0 + n];
        float* orow = out + (size_t)b2 * 1048576 + (size_t)(col0 + n) * 4096 + hw0;
#pragma unroll
        for (int it = 0; it < 4; it++) {
            int m = (it << 5) + lane;
            orow[m] = scratch[n * 132 + m] + bv;
        }
    }
}

// ---------------- windowed attention: fp32 in, bf16 h/l out ----------------
__global__ __launch_bounds__(64) void attn_kernel(const float* __restrict__ qkv,
                                                  __nv_bfloat16* __restrict__ Oh,
                                                  __nv_bfloat16* __restrict__ Ol) {
    const int h = blockIdx.x, w = blockIdx.y;
    __shared__ float4 sK[CAP][4];
    __shared__ float4 sV[CAP][4];
    const int t = threadIdx.x;
    const int T = g_win_cnt[w];
    const int* wt = &g_win_tok[w * CAP];
    for (int j = t; j < T; j += 64) {
        int tok = wt[j];
        const float4* kp = (const float4*)(qkv + (size_t)tok * 384 + 128 + h * 16);
        const float4* vp = (const float4*)(qkv + (size_t)tok * 384 + 256 + h * 16);
        sK[j][0] = kp[0]; sK[j][1] = kp[1]; sK[j][2] = kp[2]; sK[j][3] = kp[3];
        sV[j][0] = vp[0]; sV[j][1] = vp[1]; sV[j][2] = vp[2]; sV[j][3] = vp[3];
    }
    __syncthreads();
    int qtok = wt[t];
    const float4* qp = (const float4*)(qkv + (size_t)qtok * 384 + h * 16);
    float4 q0 = qp[0], q1 = qp[1], q2 = qp[2], q3 = qp[3];
    float m = -1e30f, l = 0.f;
    float4 o0 = {0,0,0,0}, o1 = {0,0,0,0}, o2 = {0,0,0,0}, o3 = {0,0,0,0};
    for (int j = 0; j < T; j++) {
        float4 k0 = sK[j][0], k1 = sK[j][1], k2 = sK[j][2], k3 = sK[j][3];
        float s = q0.x*k0.x + q0.y*k0.y + q0.z*k0.z + q0.w*k0.w
                + q1.x*k1.x + q1.y*k1.y + q1.z*k1.z + q1.w*k1.w
                + q2.x*k2.x + q2.y*k2.y + q2.z*k2.z + q2.w*k2.w
                + q3.x*k3.x + q3.y*k3.y + q3.z*k3.z + q3.w*k3.w;
        s *= 0.25f;
        float mn = fmaxf(m, s);
        float sc = __expf(m - mn);
        float p  = __expf(s - mn);
        l = l * sc + p;
        float4 v0 = sV[j][0], v1 = sV[j][1], v2 = sV[j][2], v3 = sV[j][3];
        o0.x = o0.x*sc + p*v0.x; o0.y = o0.y*sc + p*v0.y; o0.z = o0.z*sc + p*v0.z; o0.w = o0.w*sc + p*v0.w;
        o1.x = o1.x*sc + p*v1.x; o1.y = o1.y*sc + p*v1.y; o1.z = o1.z*sc + p*v1.z; o1.w = o1.w*sc + p*v1.w;
        o2.x = o2.x*sc + p*v2.x; o2.y = o2.y*sc + p*v2.y; o2.z = o2.z*sc + p*v2.z; o2.w = o2.w*sc + p*v2.w;
        o3.x = o3.x*sc + p*v3.x; o3.y = o3.y*sc + p*v3.y; o3.z = o3.z*sc + p*v3.z; o3.w = o3.w*sc + p*v3.w;
        m = mn;
    }
    float inv = 1.f / l;
    float ov[16] = { o0.x*inv, o0.y*inv, o0.z*inv, o0.w*inv,
                     o1.x*inv, o1.y*inv, o1.z*inv, o1.w*inv,
                     o2.x*inv, o2.y*inv, o2.z*inv, o2.w*inv,
                     o3.x*inv, o3.y*inv, o3.z*inv, o3.w*inv };
    uint32_t* oh32 = (uint32_t*)Oh;
    uint32_t* ol32 = (uint32_t*)Ol;
    int ob = qtok * 64 + h * 8;
#pragma unroll
    for (int j = 0; j < 8; j++) {
        uint32_t hh = bf16x2_of(ov[2*j+1], ov[2*j]);
        oh32[ob + j] = hh;
        ol32[ob + j] = bf16x2_of(ov[2*j+1] - bf16hi_f(hh), ov[2*j] - bf16lo_f(hh));
    }
}

// ============================================================================
// Fused proj + RK4 ODE (wmma bf16 h/l) — unchanged from R6.
// ============================================================================
#define ODE_SMEM 207360

__device__ __forceinline__ void mma3pass(const __nv_bfloat16* Ahs, const __nv_bfloat16* Als,
                                         const __nv_bfloat16* Bhs, const __nv_bfloat16* Bls,
                                         float* scratch, int m0, int n0) {
    wmma::fragment<wmma::accumulator, 16, 16, 16, float> acc[2][2];
#pragma unroll
    for (int mi = 0; mi < 2; mi++)
#pragma unroll
        for (int ni = 0; ni < 2; ni++)
            wmma::fill_fragment(acc[mi][ni], 0.f);
#pragma unroll
    for (int k = 0; k < 8; k++) {
        wmma::fragment<wmma::matrix_a, 16, 16, 16, __nv_bfloat16, wmma::row_major> ah0, ah1, al0, al1;
        wmma::fragment<wmma::matrix_b, 16, 16, 16, __nv_bfloat16, wmma::col_major> bh0, bh1, bl0, bl1;
        wmma::load_matrix_sync(ah0, Ahs + (size_t)m0 * 136 + k * 16, 136);
        wmma::load_matrix_sync(ah1, Ahs + (size_t)(m0 + 16) * 136 + k * 16, 136);
        wmma::load_matrix_sync(al0, Als + (size_t)m0 * 136 + k * 16, 136);
        wmma::load_matrix_sync(al1, Als + (size_t)(m0 + 16) * 136 + k * 16, 136);
        wmma::load_matrix_sync(bh0, Bhs + (size_t)n0 * 136 + k * 16, 136);
        wmma::load_matrix_sync(bh1, Bhs + (size_t)(n0 + 16) * 136 + k * 16, 136);
        wmma::load_matrix_sync(bl0, Bls + (size_t)n0 * 136 + k * 16, 136);
        wmma::load_matrix_sync(bl1, Bls + (size_t)(n0 + 16) * 136 + k * 16, 136);

        wmma::mma_sync(acc[0][0], ah0, bh0, acc[0][0]);
        wmma::mma_sync(acc[0][1], ah0, bh1, acc[0][1]);
        wmma::mma_sync(acc[1][0], ah1, bh0, acc[1][0]);
        wmma::mma_sync(acc[1][1], ah1, bh1, acc[1][1]);
        wmma::mma_sync(acc[0][0], ah0, bl0, acc[0][0]);
        wmma::mma_sync(acc[0][1], ah0, bl1, acc[0][1]);
        wmma::mma_sync(acc[1][0], ah1, bl0, acc[1][0]);
        wmma::mma_sync(acc[1][1], ah1, bl1, acc[1][1]);
        wmma::mma_sync(acc[0][0], al0, bh0, acc[0][0]);
        wmma::mma_sync(acc[0][1], al0, bh1, acc[0][1]);
        wmma::mma_sync(acc[1][0], al1, bh0, acc[1][0]);
        wmma::mma_sync(acc[1][1], al1, bh1, acc[1][1]);
    }
#pragma unroll
    for (int mi = 0; mi < 2; mi++)
#pragma unroll
        for (int ni = 0; ni < 2; ni++)
            wmma::store_matrix_sync(scratch + (size_t)(m0 + mi * 16) * 128 + n0 + ni * 16,
                                    acc[mi][ni], 128, wmma::mem_row_major);
}

__global__ __launch_bounds__(256, 1) void ode_wmma(const __nv_bfloat16* __restrict__ Oh,
                                                   const __nv_bfloat16* __restrict__ Ol,
                                                   const __nv_bfloat16* __restrict__ PWh,
                                                   const __nv_bfloat16* __restrict__ PWl,
                                                   const float* __restrict__ pbias,
                                                   const __nv_bfloat16* __restrict__ Wh_g,
                                                   const __nv_bfloat16* __restrict__ Wl_g,
                                                   const float* __restrict__ bias,
                                                   __nv_bfloat16* __restrict__ Rh,
                                                   __nv_bfloat16* __restrict__ Rl) {
    extern __shared__ __align__(16) char sm[];
    float* scratch = (float*)sm;
    float* sBias   = (float*)(sm + 32768);
    __nv_bfloat16* sWh  = (__nv_bfloat16*)(sm + 33280);
    __nv_bfloat16* sWl  = (__nv_bfloat16*)(sm + 68096);
    __nv_bfloat16* sZh  = (__nv_bfloat16*)(sm + 102912);
    __nv_bfloat16* sZl  = (__nv_bfloat16*)(sm + 120320);
    __nv_bfloat16* sPWh = (__nv_bfloat16*)(sm + 137728);
    __nv_bfloat16* sPWl = (__nv_bfloat16*)(sm + 172544);
    float* sImg = (float*)(sm + 137728);

    const int t = threadIdx.x;
    const int w = t >> 5;
    const int row0 = blockIdx.x << 6;

    {
        const uint32_t* wh32 = (const uint32_t*)Wh_g;
        const uint32_t* wl32 = (const uint32_t*)Wl_g;
        const uint32_t* ph32 = (const uint32_t*)PWh;
        const uint32_t* pl32 = (const uint32_t*)PWl;
        uint32_t* sWh32 = (uint32_t*)sWh;
        uint32_t* sWl32 = (uint32_t*)sWl;
        uint32_t* sPh32 = (uint32_t*)sPWh;
        uint32_t* sPl32 = (uint32_t*)sPWl;
        for (int idx = t; idx < 8192; idx += 256) {
            int n = idx >> 6, c2 = idx & 63;
            sWh32[n * 68 + c2] = wh32[idx];
            sWl32[n * 68 + c2] = wl32[idx];
            sPh32[n * 68 + c2] = ph32[idx];
            sPl32[n * 68 + c2] = pl32[idx];
        }
    }
    if (t < 128) sBias[t] = bias[t];
    {
        const uint32_t* oh32 = (const uint32_t*)Oh + (size_t)row0 * 64;
        const uint32_t* ol32 = (const uint32_t*)Ol + (size_t)row0 * 64;
        uint32_t* zh = (uint32_t*)sZh;
        uint32_t* zl = (uint32_t*)sZl;
        for (int idx = t; idx < 4096; idx += 256) {
            int n = idx >> 6, c2 = idx & 63;
            zh[n * 68 + c2] = oh32[idx];
            zl[n * 68 + c2] = ol32[idx];
        }
    }
    __syncthreads();

    const int wm = w >> 2, wn = w & 3;
    const int m0 = wm << 5, n0 = wn << 5;

    mma3pass(sZh, sZl, sPWh, sPWl, scratch, m0, n0);
    __syncthreads();

    const int r = t >> 2, c0 = (t & 3) << 5;
    float y[32], accv[32];
    uint32_t* zh32 = (uint32_t*)(sZh + r * 136 + c0);
    uint32_t* zl32 = (uint32_t*)(sZl + r * 136 + c0);
#pragma unroll
    for (int q = 0; q < 8; q++) {
        float4 v = *(float4*)(scratch + r * 128 + c0 + q * 4);
        float4 bb = *(const float4*)(pbias + c0 + q * 4);
        v.x += bb.x; v.y += bb.y; v.z += bb.z; v.w += bb.w;
        y[q*4] = v.x; y[q*4+1] = v.y; y[q*4+2] = v.z; y[q*4+3] = v.w;
        *(float4*)(sImg + r * 128 + c0 + q * 4) = v;
    }
#pragma unroll
    for (int j = 0; j < 16; j++) {
        float x0 = y[2*j], x1 = y[2*j+1];
        uint32_t h = bf16x2_of(x1, x0);
        zh32[j] = h;
        zl32[j] = bf16x2_of(x1 - bf16hi_f(h), x0 - bf16lo_f(h));
    }
    __syncthreads();

    for (int ev = 0; ev < 16; ev++) {
        mma3pass(sZh, sZl, sWh, sWl, scratch, m0, n0);
        __syncthreads();

        const int st = ev & 3;
        const float zc = (st < 2) ? 0.125f : 0.25f;
        const float aw = (st == 1 || st == 2) ? 2.f : 1.f;
#pragma unroll
        for (int j = 0; j < 16; j++) {
            float k0f = fmaxf(scratch[r * 128 + c0 + 2*j]     + sBias[c0 + 2*j],     0.f);
            float k1f = fmaxf(scratch[r * 128 + c0 + 2*j + 1] + sBias[c0 + 2*j + 1], 0.f);
            float a0 = (st == 0) ? k0f : accv[2*j]     + aw * k0f;
            float a1 = (st == 0) ? k1f : accv[2*j + 1] + aw * k1f;
            accv[2*j] = a0; accv[2*j+1] = a1;
            float z0, z1;
            if (st < 3) { z0 = y[2*j] + zc * k0f; z1 = y[2*j+1] + zc * k1f; }
            else {
                y[2*j]   += (1.f / 24.f) * a0;
                y[2*j+1] += (1.f / 24.f) * a1;
                z0 = y[2*j]; z1 = y[2*j+1];
            }
            uint32_t h = bf16x2_of(z1, z0);
            zh32[j] = h;
            zl32[j] = bf16x2_of(z1 - bf16hi_f(h), z0 - bf16lo_f(h));
        }
        __syncthreads();
    }

    uint32_t* rh32 = (uint32_t*)Rh;
    uint32_t* rl32 = (uint32_t*)Rl;
    int ob = (row0 + r) * 64 + (c0 >> 1);
#pragma unroll
    for (int q = 0; q < 8; q++) {
        float4 v = *(const float4*)(sImg + r * 128 + c0 + q * 4);
        float r0 = v.x + y[q*4],   r1 = v.y + y[q*4+1];
        float r2 = v.z + y[q*4+2], r3 = v.w + y[q*4+3];
        uint32_t h01 = bf16x2_of(r1, r0);
        uint32_t h23 = bf16x2_of(r3, r2);
        rh32[ob + q*2]     = h01;
        rh32[ob + q*2 + 1] = h23;
        rl32[ob + q*2]     = bf16x2_of(r1 - bf16hi_f(h01), r0 - bf16lo_f(h01));
        rl32[ob + q*2 + 1] = bf16x2_of(r3 - bf16hi_f(h23), r2 - bf16lo_f(h23));
    }
}

// ---------------- launch ----------------
extern "C" void kernel_launch(void* const* d_in, const int* in_sizes, int n_in,
                              void* d_out, int out_size) {
    const float* img   = (const float*)d_in[0];
    const int*   ptsuv = (const int*)  d_in[1];
    const float* ptsf  = (const float*)d_in[2];
    const float* wci   = (const float*)d_in[3];
    const float* bci   = (const float*)d_in[4];
    const float* wqkv  = (const float*)d_in[5];
    const float* bqkv  = (const float*)d_in[6];
    const float* wpr   = (const float*)d_in[7];
    const float* bpr   = (const float*)d_in[8];
    const float* wode  = (const float*)d_in[9];
    const float* bode  = (const float*)d_in[10];
    const float* wco   = (const float*)d_in[11];
    const float* bco   = (const float*)d_in[12];
    float* out = (float*)d_out;

    float *pqkv;
    __nv_bfloat16 *pwh, *pwl, *pfh, *pfl, *poh, *pol, *prh, *prl, *pih, *pil;
    cudaGetSymbolAddress((void**)&pqkv, g_qkv);
    cudaGetSymbolAddress((void**)&pwh,  g_wh);
    cudaGetSymbolAddress((void**)&pwl,  g_wl);
    cudaGetSymbolAddress((void**)&pfh,  g_feath);
    cudaGetSymbolAddress((void**)&pfl,  g_featl);
    cudaGetSymbolAddress((void**)&poh,  g_oh);
    cudaGetSymbolAddress((void**)&pol,  g_ol);
    cudaGetSymbolAddress((void**)&prh,  g_resh);
    cudaGetSymbolAddress((void**)&prl,  g_resl);
    cudaGetSymbolAddress((void**)&pih,  g_imgh);
    cudaGetSymbolAddress((void**)&pil,  g_imgl);

    cudaFuncSetAttribute(ode_wmma, cudaFuncAttributeMaxDynamicSharedMemorySize, ODE_SMEM);
    cudaFuncSetAttribute(wgemm,    cudaFuncAttributeMaxDynamicSharedMemorySize, WIDE_SMEM);
    cudaFuncSetAttribute(wgemm_ca, cudaFuncAttributeMaxDynamicSharedMemorySize, CA_SMEM);
    cudaFuncSetAttribute(wgemm_tr, cudaFuncAttributeMaxDynamicSharedMemorySize, WIDE_SMEM);

    // prep: weights + points + wid/hist/pixel slots + image split
    prep<<<3680, 256>>>(wci, wqkv, wpr, wode, wco, ptsf, ptsuv, img);
    pt_scatter<<<NCHUNK, 256>>>();
    // conv_in: pipelined, A col-major from split NCHW image (M=8192,N=128,K=256)
    wgemm_ca<<<dim3(1, 64), 256, CA_SMEM>>>(pih, pil, pwh + WOFF_CI, pwl + WOFF_CI,
                                            bci, pfh, pfl, 256);
    // qkv: wide (M=16384,N=384,K=128); Q col-block 0 only for pixel rows (by<64)
    wgemm<<<dim3(3, 128), 256, WIDE_SMEM>>>(pfh, pfl, pwh + WOFF_QKV, pwl + WOFF_QKV,
                                            bqkv, pqkv, 384, 128, 128, 64);
    // attention -> o h/l
    attn_kernel<<<dim3(8, 128), 64>>>(pqkv, poh, pol);
    // fused proj + RK4 ODE -> res h/l
    ode_wmma<<<128, 256, ODE_SMEM>>>(poh, pol, pwh + WOFF_PR, pwl + WOFF_PR, bpr,
                                     pwh + WOFF_ODE, pwl + WOFF_ODE, bode, prh, prl);
    // conv_out -> NCHW out (M=8192,N=256,K=128)
    wgemm_tr<<<dim3(2, 64), 256, WIDE_SMEM>>>(prh, prl, pwh + WOFF_CO, pwl + WOFF_CO,
                                              bco, out, 128);
}

// round 8
// speedup vs baseline: 1.0681x; 1.0681x over previous
#include <cuda_runtime.h>
#include <cuda_bf16.h>
#include <mma.h>
#include <cstdint>

using namespace nvcuda;

#define NPIX 8192
#define NPTS 8192
#define NTOK 16384
#define NWIN 128
#define CAP  256
#define NCHUNK 32

// ---------------- scratch (device globals; no allocation) ----------------
__device__ __nv_bfloat16 g_feath[NTOK * 128], g_featl[NTOK * 128];
__device__ float g_qkv [NTOK * 384];
__device__ __nv_bfloat16 g_oh[NPIX * 128], g_ol[NPIX * 128];
__device__ __nv_bfloat16 g_resh[NPIX * 128], g_resl[NPIX * 128];
__device__ __nv_bfloat16 g_wh[147456];
__device__ __nv_bfloat16 g_wl[147456];
__device__ int   g_ptw [NPTS];
__device__ int   g_hist[NCHUNK * NWIN];
__device__ int   g_win_tok[NWIN * CAP];
__device__ int   g_win_cnt[NWIN];

#define WOFF_CI  0
#define WOFF_QKV 32768
#define WOFF_PR  81920
#define WOFF_ODE 98304
#define WOFF_CO  114688

// ---------------- helpers ----------------
__device__ __forceinline__ uint32_t bf16x2_of(float hi, float lo) {
    uint32_t r; asm("cvt.rn.bf16x2.f32 %0, %1, %2;" : "=r"(r) : "f"(hi), "f"(lo)); return r;
}
__device__ __forceinline__ float bf16lo_f(uint32_t v) { return __uint_as_float(v << 16); }
__device__ __forceinline__ float bf16hi_f(uint32_t v) { return __uint_as_float(v & 0xffff0000u); }

__device__ __forceinline__ uint32_t smem_u32(const void* p) {
    uint32_t a;
    asm("{ .reg .u64 t; cvta.to.shared.u64 t, %1; cvt.u32.u64 %0, t; }" : "=r"(a) : "l"(p));
    return a;
}
__device__ __forceinline__ void cpa16(uint32_t s, const void* g) {
    asm volatile("cp.async.cg.shared.global [%0], [%1], 16;" :: "r"(s), "l"(g));
}
__device__ __forceinline__ void cp_commit() { asm volatile("cp.async.commit_group;" ::: "memory"); }
__device__ __forceinline__ void cp_wait1() { asm volatile("cp.async.wait_group 1;" ::: "memory"); }
__device__ __forceinline__ void cp_wait0() { asm volatile("cp.async.wait_group 0;" ::: "memory"); }

// ============================================================================
// Merged prep: weight split | points split | wid+hist+pixel slots
// ============================================================================
__global__ void prep(const float* __restrict__ wci, const float* __restrict__ wqkv,
                     const float* __restrict__ wpr, const float* __restrict__ wode,
                     const float* __restrict__ wco, const float* __restrict__ ptsf,
                     const int* __restrict__ uv) {
    __shared__ int cnt[NWIN];
    int bid = blockIdx.x, t = threadIdx.x;
    if (bid < 576) {
        int i = bid * 256 + t;
        if (i >= 147456) return;
        float x;
        if (i < WOFF_QKV)      x = wci [i];
        else if (i < WOFF_PR)  x = wqkv[i - WOFF_QKV];
        else if (i < WOFF_ODE) x = wpr [i - WOFF_PR];
        else if (i < WOFF_CO)  x = wode[i - WOFF_ODE];
        else                   x = wco [i - WOFF_CO];
        __nv_bfloat16 h = __float2bfloat16(x);
        g_wh[i] = h;
        g_wl[i] = __float2bfloat16(x - __bfloat162float(h));
    } else if (bid < 1600) {
        int i = (bid - 576) * 256 + t;
        float4 v = ((const float4*)ptsf)[i];
        uint32_t h0 = bf16x2_of(v.y, v.x);
        uint32_t h1 = bf16x2_of(v.w, v.z);
        uint32_t l0 = bf16x2_of(v.y - bf16hi_f(h0), v.x - bf16lo_f(h0));
        uint32_t l1 = bf16x2_of(v.w - bf16hi_f(h1), v.z - bf16lo_f(h1));
        uint32_t* fh = (uint32_t*)g_feath;
        uint32_t* fl = (uint32_t*)g_featl;
        int o = 524288 + 2 * i;
        fh[o] = h0; fh[o + 1] = h1;
        fl[o] = l0; fl[o + 1] = l1;
    } else {
        int c = bid - 1600;
        int i = c * 256 + t;
        if (t < NWIN) cnt[t] = 0;
        __syncthreads();
        int b = uv[3 * i] & 1;
        int u = uv[3 * i + 1] & 63;
        int v = uv[3 * i + 2] & 63;
        int wid = ((b * 8 + (v >> 3)) << 3) + (u >> 3);
        g_ptw[i] = wid;
        atomicAdd(&cnt[wid], 1);
        {
            int w = i >> 6, r = i & 63;
            int wb = w >> 6, wy = (w >> 3) & 7, wx = w & 7;
            int pv = wy * 8 + (r >> 3), pu = wx * 8 + (r & 7);
            g_win_tok[w * CAP + r] = wb * 4096 + pv * 64 + pu;
        }
        __syncthreads();
        if (t < NWIN) g_hist[c * NWIN + t] = cnt[t];
    }
}

// ---------------- scatter with inline cross-chunk scan ----------------
__global__ void pt_scatter() {
    __shared__ int cnt[NWIN];
    int t = threadIdx.x;
    int lane = t & 31;
    int c = blockIdx.x;
    int i = c * 256 + t;
    if (t < NWIN) {
        int run = 0;
        for (int cc = 0; cc < c; cc++) run += g_hist[cc * NWIN + t];
        cnt[t] = run;
        if (c == NCHUNK - 1) {
            int tot = 64 + run + g_hist[(NCHUNK - 1) * NWIN + t];
            g_win_cnt[t] = tot < CAP ? tot : CAP;
        }
    }
    __syncthreads();
    int wid = g_ptw[i];
    for (int wv = 0; wv < 8; wv++) {
        if ((t >> 5) == wv) {
            unsigned mask = __match_any_sync(0xffffffffu, wid);
            int prior = __popc(mask & ((1u << lane) - 1u));
            int base = cnt[wid];
            __syncwarp();
            int rank = 64 + base + prior;
            if (rank < CAP) g_win_tok[wid * CAP + rank] = NPIX + i;
            if (prior == 0) cnt[wid] = base + __popc(mask);
        }
        __syncthreads();
    }
}

// ============================================================================
// conv_in GEMM (R6 version): A from NCHW fp32, OUT = bf16 h/l feat.
// ============================================================================
__global__ __launch_bounds__(256) void bfgemm_ca(const float* __restrict__ img,
                                                 const __nv_bfloat16* __restrict__ Bh,
                                                 const __nv_bfloat16* __restrict__ Bl,
                                                 const float* __restrict__ bias,
                                                 __nv_bfloat16* __restrict__ Ch,
                                                 __nv_bfloat16* __restrict__ Cl, int N, int K) {
    __shared__ __align__(16) __nv_bfloat16 sAh[16 * 136], sAl[16 * 136];
    __shared__ __align__(16) __nv_bfloat16 sBh[64 * 16],  sBl[64 * 16];
    __shared__ __align__(16) float scratch[128 * 64];

    const int t = threadIdx.x;
    const int w = t >> 5;
    const int row0 = blockIdx.y << 7, col0 = blockIdx.x << 6;
    const int b = row0 >> 12, hw0 = row0 & 4095;
    const int wm = w >> 1, wn = w & 1;
    const int m0 = wm << 5, n0 = wn << 5;

    wmma::fragment<wmma::accumulator, 16, 16, 16, float> acc[2][2];
#pragma unroll
    for (int mi = 0; mi < 2; mi++)
#pragma unroll
        for (int ni = 0; ni < 2; ni++)
            wmma::fill_fragment(acc[mi][ni], 0.f);

    const uint32_t* Bh32 = (const uint32_t*)Bh;
    const uint32_t* Bl32 = (const uint32_t*)Bl;
    uint32_t* sBh32 = (uint32_t*)sBh;
    uint32_t* sBl32 = (uint32_t*)sBl;
    uint32_t* sAh32 = (uint32_t*)sAh;
    uint32_t* sAl32 = (uint32_t*)sAl;

    for (int k0 = 0; k0 < K; k0 += 16) {
#pragma unroll
        for (int i = 0; i < 2; i++) {
            int idx = t + (i << 8);
            int kk = idx >> 5, m4 = (idx & 31) << 2;
            float4 v = *(const float4*)(img + (size_t)b * 1048576 + (size_t)(k0 + kk) * 4096 + hw0 + m4);
            uint32_t h01 = bf16x2_of(v.y, v.x);
            uint32_t h23 = bf16x2_of(v.w, v.z);
            uint32_t l01 = bf16x2_of(v.y - bf16hi_f(h01), v.x - bf16lo_f(h01));
            uint32_t l23 = bf16x2_of(v.w - bf16hi_f(h23), v.z - bf16lo_f(h23));
            int so = kk * 68 + (m4 >> 1);
            sAh32[so] = h01; sAh32[so + 1] = h23;
            sAl32[so] = l01; sAl32[so + 1] = l23;
        }
#pragma unroll
        for (int i = 0; i < 2; i++) {
            int idx = t + (i << 8);
            int r = idx >> 3, c2 = idx & 7;
            size_t g = (size_t)(col0 + r) * (K >> 1) + (k0 >> 1) + c2;
            sBh32[(r << 3) + c2] = Bh32[g];
            sBl32[(r << 3) + c2] = Bl32[g];
        }
        __syncthreads();

        wmma::fragment<wmma::matrix_a, 16, 16, 16, __nv_bfloat16, wmma::col_major> ah0, ah1, al0, al1;
        wmma::fragment<wmma::matrix_b, 16, 16, 16, __nv_bfloat16, wmma::col_major> bh0, bh1, bl0, bl1;
        wmma::load_matrix_sync(ah0, sAh + m0, 136);
        wmma::load_matrix_sync(ah1, sAh + m0 + 16, 136);
        wmma::load_matrix_sync(al0, sAl + m0, 136);
        wmma::load_matrix_sync(al1, sAl + m0 + 16, 136);
        wmma::load_matrix_sync(bh0, sBh + (size_t)n0 * 16, 16);
        wmma::load_matrix_sync(bh1, sBh + (size_t)(n0 + 16) * 16, 16);
        wmma::load_matrix_sync(bl0, sBl + (size_t)n0 * 16, 16);
        wmma::load_matrix_sync(bl1, sBl + (size_t)(n0 + 16) * 16, 16);

        wmma::mma_sync(acc[0][0], ah0, bh0, acc[0][0]);
        wmma::mma_sync(acc[0][1], ah0, bh1, acc[0][1]);
        wmma::mma_sync(acc[1][0], ah1, bh0, acc[1][0]);
        wmma::mma_sync(acc[1][1], ah1, bh1, acc[1][1]);
        wmma::mma_sync(acc[0][0], ah0, bl0, acc[0][0]);
        wmma::mma_sync(acc[0][1], ah0, bl1, acc[0][1]);
        wmma::mma_sync(acc[1][0], ah1, bl0, acc[1][0]);
        wmma::mma_sync(acc[1][1], ah1, bl1, acc[1][1]);
        wmma::mma_sync(acc[0][0], al0, bh0, acc[0][0]);
        wmma::mma_sync(acc[0][1], al0, bh1, acc[0][1]);
        wmma::mma_sync(acc[1][0], al1, bh0, acc[1][0]);
        wmma::mma_sync(acc[1][1], al1, bh1, acc[1][1]);
        __syncthreads();
    }

#pragma unroll
    for (int mi = 0; mi < 2; mi++)
#pragma unroll
        for (int ni = 0; ni < 2; ni++)
            wmma::store_matrix_sync(scratch + (size_t)(m0 + mi * 16) * 64 + n0 + ni * 16,
                                    acc[mi][ni], 64, wmma::mem_row_major);
    __syncthreads();

    int r = t >> 1, cc = (t & 1) << 5;
    uint32_t* ch32 = (uint32_t*)Ch;
    uint32_t* cl32 = (uint32_t*)Cl;
#pragma unroll
    for (int q = 0; q < 8; q++) {
        float4 v = *(float4*)(scratch + r * 64 + cc + q * 4);
        float4 bb = *(const float4*)(bias + col0 + cc + q * 4);
        v.x += bb.x; v.y += bb.y; v.z += bb.z; v.w += bb.w;
        uint32_t h01 = bf16x2_of(v.y, v.x);
        uint32_t h23 = bf16x2_of(v.w, v.z);
        uint32_t l01 = bf16x2_of(v.y - bf16hi_f(h01), v.x - bf16lo_f(h01));
        uint32_t l23 = bf16x2_of(v.w - bf16hi_f(h23), v.z - bf16lo_f(h23));
        int o = (row0 + r) * (N >> 1) + ((col0 + cc) >> 1) + q * 2;
        ch32[o] = h01; ch32[o + 1] = h23;
        cl32[o] = l01; cl32[o + 1] = l23;
    }
}

// ============================================================================
// Pipelined bf16 GEMM (R6 version: 128x64 block, 60KB smem, 2 CTA/SM)
// ============================================================================
#define GBF_SMEM 61440

__global__ __launch_bounds__(256) void bfgemm_bf(const __nv_bfloat16* __restrict__ Ah,
                                                 const __nv_bfloat16* __restrict__ Al,
                                                 const __nv_bfloat16* __restrict__ Bh,
                                                 const __nv_bfloat16* __restrict__ Bl,
                                                 const float* __restrict__ bias,
                                                 float* __restrict__ C, int ldc, int K,
                                                 int qcolsplit, int qrowblk) {
    extern __shared__ __align__(16) char sm[];
    const int col0 = blockIdx.x << 6;
    if (col0 < qcolsplit && (int)blockIdx.y >= qrowblk) return;

    __nv_bfloat16* sA[4];
    __nv_bfloat16* sB[4];
    uint32_t aA[4], aB[4];
#pragma unroll
    for (int i = 0; i < 4; i++) {
        sA[i] = (__nv_bfloat16*)(sm + i * 10240);
        sB[i] = (__nv_bfloat16*)(sm + 40960 + i * 5120);
        aA[i] = smem_u32(sA[i]);
        aB[i] = smem_u32(sB[i]);
    }
    float* scratch = (float*)sm;

    const int t = threadIdx.x;
    const int w = t >> 5;
    const int row0 = blockIdx.y << 7;
    const int wm = w >> 1, wn = w & 1;
    const int m0 = wm << 5, n0 = wn << 5;

    wmma::fragment<wmma::accumulator, 16, 16, 16, float> acc[2][2];
#pragma unroll
    for (int mi = 0; mi < 2; mi++)
#pragma unroll
        for (int ni = 0; ni < 2; ni++)
            wmma::fill_fragment(acc[mi][ni], 0.f);

    const int KT = K >> 5;
    auto issue = [&](int kt, int b) {
        int k0 = kt << 5;
#pragma unroll
        for (int i = 0; i < 2; i++) {
            int id = t + (i << 8);
            int r = id >> 2, k8 = (id & 3) << 3;
            uint32_t so = (uint32_t)(r * 40 + k8) << 1;
            cpa16(aA[b] + so,     Ah + (size_t)(row0 + r) * K + k0 + k8);
            cpa16(aA[b + 2] + so, Al + (size_t)(row0 + r) * K + k0 + k8);
        }
        {
            int r = t >> 2, k8 = (t & 3) << 3;
            uint32_t so = (uint32_t)(r * 40 + k8) << 1;
            cpa16(aB[b] + so,     Bh + (size_t)(col0 + r) * K + k0 + k8);
            cpa16(aB[b + 2] + so, Bl + (size_t)(col0 + r) * K + k0 + k8);
        }
        cp_commit();
    };

    issue(0, 0);
    for (int kt = 0; kt < KT; kt++) {
        int b = kt & 1;
        if (kt + 1 < KT) { issue(kt + 1, (kt + 1) & 1); cp_wait1(); }
        else cp_wait0();
        __syncthreads();
#pragma unroll
        for (int ks = 0; ks < 2; ks++) {
            wmma::fragment<wmma::matrix_a, 16, 16, 16, __nv_bfloat16, wmma::row_major> ah0, ah1, al0, al1;
            wmma::fragment<wmma::matrix_b, 16, 16, 16, __nv_bfloat16, wmma::col_major> bh0, bh1, bl0, bl1;
            wmma::load_matrix_sync(ah0, sA[b]     + (size_t)m0 * 40 + ks * 16, 40);
            wmma::load_matrix_sync(ah1, sA[b]     + (size_t)(m0 + 16) * 40 + ks * 16, 40);
            wmma::load_matrix_sync(al0, sA[b + 2] + (size_t)m0 * 40 + ks * 16, 40);
            wmma::load_matrix_sync(al1, sA[b + 2] + (size_t)(m0 + 16) * 40 + ks * 16, 40);
            wmma::load_matrix_sync(bh0, sB[b]     + (size_t)n0 * 40 + ks * 16, 40);
            wmma::load_matrix_sync(bh1, sB[b]     + (size_t)(n0 + 16) * 40 + ks * 16, 40);
            wmma::load_matrix_sync(bl0, sB[b + 2] + (size_t)n0 * 40 + ks * 16, 40);
            wmma::load_matrix_sync(bl1, sB[b + 2] + (size_t)(n0 + 16) * 40 + ks * 16, 40);

            wmma::mma_sync(acc[0][0], ah0, bh0, acc[0][0]);
            wmma::mma_sync(acc[0][1], ah0, bh1, acc[0][1]);
            wmma::mma_sync(acc[1][0], ah1, bh0, acc[1][0]);
            wmma::mma_sync(acc[1][1], ah1, bh1, acc[1][1]);
            wmma::mma_sync(acc[0][0], ah0, bl0, acc[0][0]);
            wmma::mma_sync(acc[0][1], ah0, bl1, acc[0][1]);
            wmma::mma_sync(acc[1][0], ah1, bl0, acc[1][0]);
            wmma::mma_sync(acc[1][1], ah1, bl1, acc[1][1]);
            wmma::mma_sync(acc[0][0], al0, bh0, acc[0][0]);
            wmma::mma_sync(acc[0][1], al0, bh1, acc[0][1]);
            wmma::mma_sync(acc[1][0], al1, bh0, acc[1][0]);
            wmma::mma_sync(acc[1][1], al1, bh1, acc[1][1]);
        }
        __syncthreads();
    }

#pragma unroll
    for (int mi = 0; mi < 2; mi++)
#pragma unroll
        for (int ni = 0; ni < 2; ni++)
            wmma::store_matrix_sync(scratch + (size_t)(m0 + mi * 16) * 64 + n0 + ni * 16,
                                    acc[mi][ni], 64, wmma::mem_row_major);
    __syncthreads();

    int r = t >> 1, cc = (t & 1) << 5;
#pragma unroll
    for (int q = 0; q < 8; q++) {
        float4 v = *(float4*)(scratch + r * 64 + cc + q * 4);
        float4 bb = *(const float4*)(bias + col0 + cc + q * 4);
        v.x += bb.x; v.y += bb.y; v.z += bb.z; v.w += bb.w;
        *(float4*)(C + (size_t)(row0 + r) * ldc + col0 + cc + q * 4) = v;
    }
}

// ============================================================================
// conv_out (R6 version): pipelined bf16 GEMM with transposed NCHW store.
// ============================================================================
#define GTR_SMEM 61440

__global__ __launch_bounds__(256) void bfgemm_tr_bf(const __nv_bfloat16* __restrict__ Ah,
                                                    const __nv_bfloat16* __restrict__ Al,
                                                    const __nv_bfloat16* __restrict__ Bh,
                                                    const __nv_bfloat16* __restrict__ Bl,
                                                    const float* __restrict__ bias,
                                                    float* __restrict__ out, int K) {
    extern __shared__ __align__(16) char sm[];
    __nv_bfloat16* sA[4];
    __nv_bfloat16* sB[4];
    uint32_t aA[4], aB[4];
#pragma unroll
    for (int i = 0; i < 4; i++) {
        sA[i] = (__nv_bfloat16*)(sm + i * 10240);
        sB[i] = (__nv_bfloat16*)(sm + 40960 + i * 5120);
        aA[i] = smem_u32(sA[i]);
        aB[i] = smem_u32(sB[i]);
    }
    float* scratch = (float*)sm;

    const int t = threadIdx.x;
    const int w = t >> 5;
    const int row0 = blockIdx.y << 7, col0 = blockIdx.x << 6;
    const int b2 = row0 >> 12, hw0 = row0 & 4095;
    const int wm = w >> 1, wn = w & 1;
    const int m0 = wm << 5, n0 = wn << 5;

    wmma::fragment<wmma::accumulator, 16, 16, 16, float> acc[2][2];
#pragma unroll
    for (int mi = 0; mi < 2; mi++)
#pragma unroll
        for (int ni = 0; ni < 2; ni++)
            wmma::fill_fragment(acc[mi][ni], 0.f);

    const int KT = K >> 5;
    auto issue = [&](int kt, int b) {
        int k0 = kt << 5;
#pragma unroll
        for (int i = 0; i < 2; i++) {
            int id = t + (i << 8);
            int r = id >> 2, k8 = (id & 3) << 3;
            uint32_t so = (uint32_t)(r * 40 + k8) << 1;
            cpa16(aA[b] + so,     Ah + (size_t)(row0 + r) * K + k0 + k8);
            cpa16(aA[b + 2] + so, Al + (size_t)(row0 + r) * K + k0 + k8);
        }
        {
            int r = t >> 2, k8 = (t & 3) << 3;
            uint32_t so = (uint32_t)(r * 40 + k8) << 1;
            cpa16(aB[b] + so,     Bh + (size_t)(col0 + r) * K + k0 + k8);
            cpa16(aB[b + 2] + so, Bl + (size_t)(col0 + r) * K + k0 + k8);
        }
        cp_commit();
    };

    issue(0, 0);
    for (int kt = 0; kt < KT; kt++) {
        int b = kt & 1;
        if (kt + 1 < KT) { issue(kt + 1, (kt + 1) & 1); cp_wait1(); }
        else cp_wait0();
        __syncthreads();
#pragma unroll
        for (int ks = 0; ks < 2; ks++) {
            wmma::fragment<wmma::matrix_a, 16, 16, 16, __nv_bfloat16, wmma::row_major> ah0, ah1, al0, al1;
            wmma::fragment<wmma::matrix_b, 16, 16, 16, __nv_bfloat16, wmma::col_major> bh0, bh1, bl0, bl1;
            wmma::load_matrix_sync(ah0, sA[b]     + (size_t)m0 * 40 + ks * 16, 40);
            wmma::load_matrix_sync(ah1, sA[b]     + (size_t)(m0 + 16) * 40 + ks * 16, 40);
            wmma::load_matrix_sync(al0, sA[b + 2] + (size_t)m0 * 40 + ks * 16, 40);
            wmma::load_matrix_sync(al1, sA[b + 2] + (size_t)(m0 + 16) * 40 + ks * 16, 40);
            wmma::load_matrix_sync(bh0, sB[b]     + (size_t)n0 * 40 + ks * 16, 40);
            wmma::load_matrix_sync(bh1, sB[b]     + (size_t)(n0 + 16) * 40 + ks * 16, 40);
            wmma::load_matrix_sync(bl0, sB[b + 2] + (size_t)n0 * 40 + ks * 16, 40);
            wmma::load_matrix_sync(bl1, sB[b + 2] + (size_t)(n0 + 16) * 40 + ks * 16, 40);

            wmma::mma_sync(acc[0][0], ah0, bh0, acc[0][0]);
            wmma::mma_sync(acc[0][1], ah0, bh1, acc[0][1]);
            wmma::mma_sync(acc[1][0], ah1, bh0, acc[1][0]);
            wmma::mma_sync(acc[1][1], ah1, bh1, acc[1][1]);
            wmma::mma_sync(acc[0][0], ah0, bl0, acc[0][0]);
            wmma::mma_sync(acc[0][1], ah0, bl1, acc[0][1]);
            wmma::mma_sync(acc[1][0], ah1, bl0, acc[1][0]);
            wmma::mma_sync(acc[1][1], ah1, bl1, acc[1][1]);
            wmma::mma_sync(acc[0][0], al0, bh0, acc[0][0]);
            wmma::mma_sync(acc[0][1], al0, bh1, acc[0][1]);
            wmma::mma_sync(acc[1][0], al1, bh0, acc[1][0]);
            wmma::mma_sync(acc[1][1], al1, bh1, acc[1][1]);
        }
        __syncthreads();
    }

#pragma unroll
    for (int mi = 0; mi < 2; mi++)
#pragma unroll
        for (int ni = 0; ni < 2; ni++)
            wmma::store_matrix_sync(scratch + (size_t)(n0 + ni * 16) * 132 + m0 + mi * 16,
                                    acc[mi][ni], 132, wmma::mem_col_major);
    __syncthreads();

    const int lane = t & 31;
#pragma unroll
    for (int nn = 0; nn < 8; nn++) {
        int n = (w << 3) + nn;
        float bv = bias[col0 + n];
        float* orow = out + (size_t)b2 * 1048576 + (size_t)(col0 + n) * 4096 + hw0;
#pragma unroll
        for (int it = 0; it < 4; it++) {
            int m = (it << 5) + lane;
            orow[m] = scratch[n * 132 + m] + bv;
        }
    }
}

// ============================================================================
// Windowed attention, 4-way key-split: 256 threads = 64 queries x 4 segments.
// Deterministic partial-softmax merge via padded smem.
// smem: sK 16384 | sV 16384 | pm 1024 | pl 1024 | po 4*64*17*4=17408 -> 52224
// ============================================================================
#define ATTN_SMEM 52224

__global__ __launch_bounds__(256) void attn_kernel(const float* __restrict__ qkv,
                                                   __nv_bfloat16* __restrict__ Oh,
                                                   __nv_bfloat16* __restrict__ Ol) {
    extern __shared__ __align__(16) char asmem[];
    float4 (*sK)[4] = (float4(*)[4])asmem;
    float4 (*sV)[4] = (float4(*)[4])(asmem + 16384);
    float* pm = (float*)(asmem + 32768);
    float* pl = (float*)(asmem + 33792);
    float* po = (float*)(asmem + 34816);

    const int h = blockIdx.x, w = blockIdx.y;
    const int t = threadIdx.x;
    const int sg = t >> 6, q = t & 63;
    const int T = g_win_cnt[w];
    const int* wt = &g_win_tok[w * CAP];

    for (int j = t; j < T; j += 256) {
        int tok = wt[j];
        const float4* kp = (const float4*)(qkv + (size_t)tok * 384 + 128 + h * 16);
        const float4* vp = (const float4*)(qkv + (size_t)tok * 384 + 256 + h * 16);
        sK[j][0] = kp[0]; sK[j][1] = kp[1]; sK[j][2] = kp[2]; sK[j][3] = kp[3];
        sV[j][0] = vp[0]; sV[j][1] = vp[1]; sV[j][2] = vp[2]; sV[j][3] = vp[3];
    }
    __syncthreads();

    const int qtok = wt[q];
    const float4* qp = (const float4*)(qkv + (size_t)qtok * 384 + h * 16);
    float4 q0 = qp[0], q1 = qp[1], q2 = qp[2], q3 = qp[3];

    const int j0 = (T * sg) >> 2, j1 = (T * (sg + 1)) >> 2;
    float m = -1e30f, l = 0.f;
    float4 o0 = {0,0,0,0}, o1 = {0,0,0,0}, o2 = {0,0,0,0}, o3 = {0,0,0,0};
    for (int j = j0; j < j1; j++) {
        float4 k0 = sK[j][0], k1 = sK[j][1], k2 = sK[j][2], k3 = sK[j][3];
        float s = q0.x*k0.x + q0.y*k0.y + q0.z*k0.z + q0.w*k0.w
                + q1.x*k1.x + q1.y*k1.y + q1.z*k1.z + q1.w*k1.w
                + q2.x*k2.x + q2.y*k2.y + q2.z*k2.z + q2.w*k2.w
                + q3.x*k3.x + q3.y*k3.y + q3.z*k3.z + q3.w*k3.w;
        s *= 0.25f;
        float mn = fmaxf(m, s);
        float sc = __expf(m - mn);
        float p  = __expf(s - mn);
        l = l * sc + p;
        float4 v0 = sV[j][0], v1 = sV[j][1], v2 = sV[j][2], v3 = sV[j][3];
        o0.x = o0.x*sc + p*v0.x; o0.y = o0.y*sc + p*v0.y; o0.z = o0.z*sc + p*v0.z; o0.w = o0.w*sc + p*v0.w;
        o1.x = o1.x*sc + p*v1.x; o1.y = o1.y*sc + p*v1.y; o1.z = o1.z*sc + p*v1.z; o1.w = o1.w*sc + p*v1.w;
        o2.x = o2.x*sc + p*v2.x; o2.y = o2.y*sc + p*v2.y; o2.z = o2.z*sc + p*v2.z; o2.w = o2.w*sc + p*v2.w;
        o3.x = o3.x*sc + p*v3.x; o3.y = o3.y*sc + p*v3.y; o3.z = o3.z*sc + p*v3.z; o3.w = o3.w*sc + p*v3.w;
        m = mn;
    }
    pm[t] = m;
    pl[t] = l;
    float* pop = po + (sg * 64 + q) * 17;
    pop[0] = o0.x; pop[1] = o0.y; pop[2]  = o0.z; pop[3]  = o0.w;
    pop[4] = o1.x; pop[5] = o1.y; pop[6]  = o1.z; pop[7]  = o1.w;
    pop[8] = o2.x; pop[9] = o2.y; pop[10] = o2.z; pop[11] = o2.w;
    pop[12] = o3.x; pop[13] = o3.y; pop[14] = o3.z; pop[15] = o3.w;
    __syncthreads();

    if (t < 64) {
        float m0 = pm[q], m1 = pm[64 + q], m2 = pm[128 + q], m3 = pm[192 + q];
        float mm = fmaxf(fmaxf(m0, m1), fmaxf(m2, m3));
        float e0 = __expf(m0 - mm), e1 = __expf(m1 - mm);
        float e2 = __expf(m2 - mm), e3 = __expf(m3 - mm);
        float lt = pl[q] * e0 + pl[64 + q] * e1 + pl[128 + q] * e2 + pl[192 + q] * e3;
        float inv = 1.f / lt;
        const float* p0 = po + q * 17;
        const float* p1 = po + (64 + q) * 17;
        const float* p2 = po + (128 + q) * 17;
        const float* p3 = po + (192 + q) * 17;
        uint32_t* oh32 = (uint32_t*)Oh;
        uint32_t* ol32 = (uint32_t*)Ol;
        int ob = qtok * 64 + h * 8;
#pragma unroll
        for (int j = 0; j < 8; j++) {
            float vlo = (p0[2*j]   * e0 + p1[2*j]   * e1 + p2[2*j]   * e2 + p3[2*j]   * e3) * inv;
            float vhi = (p0[2*j+1] * e0 + p1[2*j+1] * e1 + p2[2*j+1] * e2 + p3[2*j+1] * e3) * inv;
            uint32_t hh = bf16x2_of(vhi, vlo);
            oh32[ob + j] = hh;
            ol32[ob + j] = bf16x2_of(vhi - bf16hi_f(hh), vlo - bf16lo_f(hh));
        }
    }
}

// ============================================================================
// Fused proj + RK4 ODE (R6 version, unchanged)
// ============================================================================
#define ODE_SMEM 207360

__device__ __forceinline__ void mma3pass(const __nv_bfloat16* Ahs, const __nv_bfloat16* Als,
                                         const __nv_bfloat16* Bhs, const __nv_bfloat16* Bls,
                                         float* scratch, int m0, int n0) {
    wmma::fragment<wmma::accumulator, 16, 16, 16, float> acc[2][2];
#pragma unroll
    for (int mi = 0; mi < 2; mi++)
#pragma unroll
        for (int ni = 0; ni < 2; ni++)
            wmma::fill_fragment(acc[mi][ni], 0.f);
#pragma unroll
    for (int k = 0; k < 8; k++) {
        wmma::fragment<wmma::matrix_a, 16, 16, 16, __nv_bfloat16, wmma::row_major> ah0, ah1, al0, al1;
        wmma::fragment<wmma::matrix_b, 16, 16, 16, __nv_bfloat16, wmma::col_major> bh0, bh1, bl0, bl1;
        wmma::load_matrix_sync(ah0, Ahs + (size_t)m0 * 136 + k * 16, 136);
        wmma::load_matrix_sync(ah1, Ahs + (size_t)(m0 + 16) * 136 + k * 16, 136);
        wmma::load_matrix_sync(al0, Als + (size_t)m0 * 136 + k * 16, 136);
        wmma::load_matrix_sync(al1, Als + (size_t)(m0 + 16) * 136 + k * 16, 136);
        wmma::load_matrix_sync(bh0, Bhs + (size_t)n0 * 136 + k * 16, 136);
        wmma::load_matrix_sync(bh1, Bhs + (size_t)(n0 + 16) * 136 + k * 16, 136);
        wmma::load_matrix_sync(bl0, Bls + (size_t)n0 * 136 + k * 16, 136);
        wmma::load_matrix_sync(bl1, Bls + (size_t)(n0 + 16) * 136 + k * 16, 136);

        wmma::mma_sync(acc[0][0], ah0, bh0, acc[0][0]);
        wmma::mma_sync(acc[0][1], ah0, bh1, acc[0][1]);
        wmma::mma_sync(acc[1][0], ah1, bh0, acc[1][0]);
        wmma::mma_sync(acc[1][1], ah1, bh1, acc[1][1]);
        wmma::mma_sync(acc[0][0], ah0, bl0, acc[0][0]);
        wmma::mma_sync(acc[0][1], ah0, bl1, acc[0][1]);
        wmma::mma_sync(acc[1][0], ah1, bl0, acc[1][0]);
        wmma::mma_sync(acc[1][1], ah1, bl1, acc[1][1]);
        wmma::mma_sync(acc[0][0], al0, bh0, acc[0][0]);
        wmma::mma_sync(acc[0][1], al0, bh1, acc[0][1]);
        wmma::mma_sync(acc[1][0], al1, bh0, acc[1][0]);
        wmma::mma_sync(acc[1][1], al1, bh1, acc[1][1]);
    }
#pragma unroll
    for (int mi = 0; mi < 2; mi++)
#pragma unroll
        for (int ni = 0; ni < 2; ni++)
            wmma::store_matrix_sync(scratch + (size_t)(m0 + mi * 16) * 128 + n0 + ni * 16,
                                    acc[mi][ni], 128, wmma::mem_row_major);
}

__global__ __launch_bounds__(256, 1) void ode_wmma(const __nv_bfloat16* __restrict__ Oh,
                                                   const __nv_bfloat16* __restrict__ Ol,
                                                   const __nv_bfloat16* __restrict__ PWh,
                                                   const __nv_bfloat16* __restrict__ PWl,
                                                   const float* __restrict__ pbias,
                                                   const __nv_bfloat16* __restrict__ Wh_g,
                                                   const __nv_bfloat16* __restrict__ Wl_g,
                                                   const float* __restrict__ bias,
                                                   __nv_bfloat16* __restrict__ Rh,
                                                   __nv_bfloat16* __restrict__ Rl) {
    extern __shared__ __align__(16) char sm[];
    float* scratch = (float*)sm;
    float* sBias   = (float*)(sm + 32768);
    __nv_bfloat16* sWh  = (__nv_bfloat16*)(sm + 33280);
    __nv_bfloat16* sWl  = (__nv_bfloat16*)(sm + 68096);
    __nv_bfloat16* sZh  = (__nv_bfloat16*)(sm + 102912);
    __nv_bfloat16* sZl  = (__nv_bfloat16*)(sm + 120320);
    __nv_bfloat16* sPWh = (__nv_bfloat16*)(sm + 137728);
    __nv_bfloat16* sPWl = (__nv_bfloat16*)(sm + 172544);
    float* sImg = (float*)(sm + 137728);

    const int t = threadIdx.x;
    const int w = t >> 5;
    const int row0 = blockIdx.x << 6;

    {
        const uint32_t* wh32 = (const uint32_t*)Wh_g;
        const uint32_t* wl32 = (const uint32_t*)Wl_g;
        const uint32_t* ph32 = (const uint32_t*)PWh;
        const uint32_t* pl32 = (const uint32_t*)PWl;
        uint32_t* sWh32 = (uint32_t*)sWh;
        uint32_t* sWl32 = (uint32_t*)sWl;
        uint32_t* sPh32 = (uint32_t*)sPWh;
        uint32_t* sPl32 = (uint32_t*)sPWl;
        for (int idx = t; idx < 8192; idx += 256) {
            int n = idx >> 6, c2 = idx & 63;
            sWh32[n * 68 + c2] = wh32[idx];
            sWl32[n * 68 + c2] = wl32[idx];
            sPh32[n * 68 + c2] = ph32[idx];
            sPl32[n * 68 + c2] = pl32[idx];
        }
    }
    if (t < 128) sBias[t] = bias[t];
    {
        const uint32_t* oh32 = (const uint32_t*)Oh + (size_t)row0 * 64;
        const uint32_t* ol32 = (const uint32_t*)Ol + (size_t)row0 * 64;
        uint32_t* zh = (uint32_t*)sZh;
        uint32_t* zl = (uint32_t*)sZl;
        for (int idx = t; idx < 4096; idx += 256) {
            int n = idx >> 6, c2 = idx & 63;
            zh[n * 68 + c2] = oh32[idx];
            zl[n * 68 + c2] = ol32[idx];
        }
    }
    __syncthreads();

    const int wm = w >> 2, wn = w & 3;
    const int m0 = wm << 5, n0 = wn << 5;

    mma3pass(sZh, sZl, sPWh, sPWl, scratch, m0, n0);
    __syncthreads();

    const int r = t >> 2, c0 = (t & 3) << 5;
    float y[32], accv[32];
    uint32_t* zh32 = (uint32_t*)(sZh + r * 136 + c0);
    uint32_t* zl32 = (uint32_t*)(sZl + r * 136 + c0);
#pragma unroll
    for (int q = 0; q < 8; q++) {
        float4 v = *(float4*)(scratch + r * 128 + c0 + q * 4);
        float4 bb = *(const float4*)(pbias + c0 + q * 4);
        v.x += bb.x; v.y += bb.y; v.z += bb.z; v.w += bb.w;
        y[q*4] = v.x; y[q*4+1] = v.y; y[q*4+2] = v.z; y[q*4+3] = v.w;
        *(float4*)(sImg + r * 128 + c0 + q * 4) = v;
    }
#pragma unroll
    for (int j = 0; j < 16; j++) {
        float x0 = y[2*j], x1 = y[2*j+1];
        uint32_t h = bf16x2_of(x1, x0);
        zh32[j] = h;
        zl32[j] = bf16x2_of(x1 - bf16hi_f(h), x0 - bf16lo_f(h));
    }
    __syncthreads();

    for (int ev = 0; ev < 16; ev++) {
        mma3pass(sZh, sZl, sWh, sWl, scratch, m0, n0);
        __syncthreads();

        const int st = ev & 3;
        const float zc = (st < 2) ? 0.125f : 0.25f;
        const float aw = (st == 1 || st == 2) ? 2.f : 1.f;
#pragma unroll
        for (int j = 0; j < 16; j++) {
            float k0f = fmaxf(scratch[r * 128 + c0 + 2*j]     + sBias[c0 + 2*j],     0.f);
            float k1f = fmaxf(scratch[r * 128 + c0 + 2*j + 1] + sBias[c0 + 2*j + 1], 0.f);
            float a0 = (st == 0) ? k0f : accv[2*j]     + aw * k0f;
            float a1 = (st == 0) ? k1f : accv[2*j + 1] + aw * k1f;
            accv[2*j] = a0; accv[2*j+1] = a1;
            float z0, z1;
            if (st < 3) { z0 = y[2*j] + zc * k0f; z1 = y[2*j+1] + zc * k1f; }
            else {
                y[2*j]   += (1.f / 24.f) * a0;
                y[2*j+1] += (1.f / 24.f) * a1;
                z0 = y[2*j]; z1 = y[2*j+1];
            }
            uint32_t h = bf16x2_of(z1, z0);
            zh32[j] = h;
            zl32[j] = bf16x2_of(z1 - bf16hi_f(h), z0 - bf16lo_f(h));
        }
        __syncthreads();
    }

    uint32_t* rh32 = (uint32_t*)Rh;
    uint32_t* rl32 = (uint32_t*)Rl;
    int ob = (row0 + r) * 64 + (c0 >> 1);
#pragma unroll
    for (int q = 0; q < 8; q++) {
        float4 v = *(const float4*)(sImg + r * 128 + c0 + q * 4);
        float r0 = v.x + y[q*4],   r1 = v.y + y[q*4+1];
        float r2 = v.z + y[q*4+2], r3 = v.w + y[q*4+3];
        uint32_t h01 = bf16x2_of(r1, r0);
        uint32_t h23 = bf16x2_of(r3, r2);
        rh32[ob + q*2]     = h01;
        rh32[ob + q*2 + 1] = h23;
        rl32[ob + q*2]     = bf16x2_of(r1 - bf16hi_f(h01), r0 - bf16lo_f(h01));
        rl32[ob + q*2 + 1] = bf16x2_of(r3 - bf16hi_f(h23), r2 - bf16lo_f(h23));
    }
}

// ---------------- launch ----------------
extern "C" void kernel_launch(void* const* d_in, const int* in_sizes, int n_in,
                              void* d_out, int out_size) {
    const float* img   = (const float*)d_in[0];
    const int*   ptsuv = (const int*)  d_in[1];
    const float* ptsf  = (const float*)d_in[2];
    const float* wci   = (const float*)d_in[3];
    const float* bci   = (const float*)d_in[4];
    const float* wqkv  = (const float*)d_in[5];
    const float* bqkv  = (const float*)d_in[6];
    const float* wpr   = (const float*)d_in[7];
    const float* bpr   = (const float*)d_in[8];
    const float* wode  = (const float*)d_in[9];
    const float* bode  = (const float*)d_in[10];
    const float* wco   = (const float*)d_in[11];
    const float* bco   = (const float*)d_in[12];
    float* out = (float*)d_out;

    float *pqkv;
    __nv_bfloat16 *pwh, *pwl, *pfh, *pfl, *poh, *pol, *prh, *prl;
    cudaGetSymbolAddress((void**)&pqkv, g_qkv);
    cudaGetSymbolAddress((void**)&pwh,  g_wh);
    cudaGetSymbolAddress((void**)&pwl,  g_wl);
    cudaGetSymbolAddress((void**)&pfh,  g_feath);
    cudaGetSymbolAddress((void**)&pfl,  g_featl);
    cudaGetSymbolAddress((void**)&poh,  g_oh);
    cudaGetSymbolAddress((void**)&pol,  g_ol);
    cudaGetSymbolAddress((void**)&prh,  g_resh);
    cudaGetSymbolAddress((void**)&prl,  g_resl);

    cudaFuncSetAttribute(ode_wmma,     cudaFuncAttributeMaxDynamicSharedMemorySize, ODE_SMEM);
    cudaFuncSetAttribute(bfgemm_bf,    cudaFuncAttributeMaxDynamicSharedMemorySize, GBF_SMEM);
    cudaFuncSetAttribute(bfgemm_tr_bf, cudaFuncAttributeMaxDynamicSharedMemorySize, GTR_SMEM);
    cudaFuncSetAttribute(attn_kernel,  cudaFuncAttributeMaxDynamicSharedMemorySize, ATTN_SMEM);

    prep<<<1632, 256>>>(wci, wqkv, wpr, wode, wco, ptsf, ptsuv);
    pt_scatter<<<NCHUNK, 256>>>();
    // conv_in from NCHW -> feat h/l
    bfgemm_ca<<<dim3(2, 64), 256>>>(img, pwh + WOFF_CI, pwl + WOFF_CI, bci, pfh, pfl, 128, 256);
    // qkv merged: Q (cols<128) only for pixel rows (by<64)
    bfgemm_bf<<<dim3(6, 128), 256, GBF_SMEM>>>(pfh, pfl, pwh + WOFF_QKV, pwl + WOFF_QKV,
                                               bqkv, pqkv, 384, 128, 128, 64);
    // attention (4-way key split) -> o h/l
    attn_kernel<<<dim3(8, 128), 256, ATTN_SMEM>>>(pqkv, poh, pol);
    // fused proj + RK4 ODE -> res h/l
    ode_wmma<<<128, 256, ODE_SMEM>>>(poh, pol, pwh + WOFF_PR, pwl + WOFF_PR, bpr,
                                     pwh + WOFF_ODE, pwl + WOFF_ODE, bode, prh, prl);
    // conv_out -> NCHW out
    bfgemm_tr_bf<<<dim3(4, 64), 256, GTR_SMEM>>>(prh, prl, pwh + WOFF_CO, pwl + WOFF_CO,
                                                 bco, out, 128);
}

// round 9
// speedup vs baseline: 1.5181x; 1.4213x over previous
#include <cuda_runtime.h>
#include <cuda_bf16.h>
#include <mma.h>
#include <cstdint>

using namespace nvcuda;

#define NPIX 8192
#define NPTS 8192
#define NTOK 16384
#define NWIN 128
#define CAP  256
#define NCHUNK 32

// ---------------- scratch (device globals; no allocation) ----------------
__device__ __nv_bfloat16 g_feath[NTOK * 128], g_featl[NTOK * 128];
__device__ float g_qkv [NTOK * 384];
__device__ __nv_bfloat16 g_oh[NPIX * 128], g_ol[NPIX * 128];
__device__ __nv_bfloat16 g_resh[NPIX * 128], g_resl[NPIX * 128];
__device__ __nv_bfloat16 g_wh[147456];
__device__ __nv_bfloat16 g_wl[147456];
__device__ int   g_ptw [NPTS];
__device__ int   g_hist[NCHUNK * NWIN];
__device__ int   g_win_tok[NWIN * CAP];
__device__ int   g_win_cnt[NWIN];

#define WOFF_CI  0
#define WOFF_QKV 32768
#define WOFF_PR  81920
#define WOFF_ODE 98304
#define WOFF_CO  114688

// ---------------- helpers ----------------
__device__ __forceinline__ uint32_t bf16x2_of(float hi, float lo) {
    uint32_t r; asm("cvt.rn.bf16x2.f32 %0, %1, %2;" : "=r"(r) : "f"(hi), "f"(lo)); return r;
}
__device__ __forceinline__ float bf16lo_f(uint32_t v) { return __uint_as_float(v << 16); }
__device__ __forceinline__ float bf16hi_f(uint32_t v) { return __uint_as_float(v & 0xffff0000u); }

__device__ __forceinline__ uint32_t smem_u32(const void* p) {
    uint32_t a;
    asm("{ .reg .u64 t; cvta.to.shared.u64 t, %1; cvt.u32.u64 %0, t; }" : "=r"(a) : "l"(p));
    return a;
}
__device__ __forceinline__ void cpa16(uint32_t s, const void* g) {
    asm volatile("cp.async.cg.shared.global [%0], [%1], 16;" :: "r"(s), "l"(g));
}
__device__ __forceinline__ void cp_commit() { asm volatile("cp.async.commit_group;" ::: "memory"); }
__device__ __forceinline__ void cp_wait1() { asm volatile("cp.async.wait_group 1;" ::: "memory"); }
__device__ __forceinline__ void cp_wait0() { asm volatile("cp.async.wait_group 0;" ::: "memory"); }

__device__ __forceinline__ void ldm4(uint32_t* r, uint32_t addr) {
    asm volatile("ldmatrix.sync.aligned.m8n8.x4.shared.b16 {%0,%1,%2,%3}, [%4];"
                 : "=r"(r[0]), "=r"(r[1]), "=r"(r[2]), "=r"(r[3]) : "r"(addr));
}
__device__ __forceinline__ void mma16816(float* d, const uint32_t* a, uint32_t b0, uint32_t b1) {
    asm volatile("mma.sync.aligned.m16n8k16.row.col.f32.bf16.bf16.f32 "
                 "{%0,%1,%2,%3}, {%4,%5,%6,%7}, {%8,%9}, {%0,%1,%2,%3};"
                 : "+f"(d[0]), "+f"(d[1]), "+f"(d[2]), "+f"(d[3])
                 : "r"(a[0]), "r"(a[1]), "r"(a[2]), "r"(a[3]), "r"(b0), "r"(b1));
}

// ============================================================================
// Merged prep: weight split | points split | wid+hist+pixel slots
// ============================================================================
__global__ void prep(const float* __restrict__ wci, const float* __restrict__ wqkv,
                     const float* __restrict__ wpr, const float* __restrict__ wode,
                     const float* __restrict__ wco, const float* __restrict__ ptsf,
                     const int* __restrict__ uv) {
    __shared__ int cnt[NWIN];
    int bid = blockIdx.x, t = threadIdx.x;
    if (bid < 576) {
        int i = bid * 256 + t;
        if (i >= 147456) return;
        float x;
        if (i < WOFF_QKV)      x = wci [i];
        else if (i < WOFF_PR)  x = wqkv[i - WOFF_QKV];
        else if (i < WOFF_ODE) x = wpr [i - WOFF_PR];
        else if (i < WOFF_CO)  x = wode[i - WOFF_ODE];
        else                   x = wco [i - WOFF_CO];
        __nv_bfloat16 h = __float2bfloat16(x);
        g_wh[i] = h;
        g_wl[i] = __float2bfloat16(x - __bfloat162float(h));
    } else if (bid < 1600) {
        int i = (bid - 576) * 256 + t;
        float4 v = ((const float4*)ptsf)[i];
        uint32_t h0 = bf16x2_of(v.y, v.x);
        uint32_t h1 = bf16x2_of(v.w, v.z);
        uint32_t l0 = bf16x2_of(v.y - bf16hi_f(h0), v.x - bf16lo_f(h0));
        uint32_t l1 = bf16x2_of(v.w - bf16hi_f(h1), v.z - bf16lo_f(h1));
        uint32_t* fh = (uint32_t*)g_feath;
        uint32_t* fl = (uint32_t*)g_featl;
        int o = 524288 + 2 * i;
        fh[o] = h0; fh[o + 1] = h1;
        fl[o] = l0; fl[o + 1] = l1;
    } else {
        int c = bid - 1600;
        int i = c * 256 + t;
        if (t < NWIN) cnt[t] = 0;
        __syncthreads();
        int b = uv[3 * i] & 1;
        int u = uv[3 * i + 1] & 63;
        int v = uv[3 * i + 2] & 63;
        int wid = ((b * 8 + (v >> 3)) << 3) + (u >> 3);
        g_ptw[i] = wid;
        atomicAdd(&cnt[wid], 1);
        {
            int w = i >> 6, r = i & 63;
            int wb = w >> 6, wy = (w >> 3) & 7, wx = w & 7;
            int pv = wy * 8 + (r >> 3), pu = wx * 8 + (r & 7);
            g_win_tok[w * CAP + r] = wb * 4096 + pv * 64 + pu;
        }
        __syncthreads();
        if (t < NWIN) g_hist[c * NWIN + t] = cnt[t];
    }
}

// ---------------- scatter with inline cross-chunk scan ----------------
__global__ void pt_scatter() {
    __shared__ int cnt[NWIN];
    int t = threadIdx.x;
    int lane = t & 31;
    int c = blockIdx.x;
    int i = c * 256 + t;
    if (t < NWIN) {
        int run = 0;
        for (int cc = 0; cc < c; cc++) run += g_hist[cc * NWIN + t];
        cnt[t] = run;
        if (c == NCHUNK - 1) {
            int tot = 64 + run + g_hist[(NCHUNK - 1) * NWIN + t];
            g_win_cnt[t] = tot < CAP ? tot : CAP;
        }
    }
    __syncthreads();
    int wid = g_ptw[i];
    for (int wv = 0; wv < 8; wv++) {
        if ((t >> 5) == wv) {
            unsigned mask = __match_any_sync(0xffffffffu, wid);
            int prior = __popc(mask & ((1u << lane) - 1u));
            int base = cnt[wid];
            __syncwarp();
            int rank = 64 + base + prior;
            if (rank < CAP) g_win_tok[wid * CAP + rank] = NPIX + i;
            if (prior == 0) cnt[wid] = base + __popc(mask);
        }
        __syncthreads();
    }
}

// ============================================================================
// conv_in GEMM (R6/R8 version): A from NCHW fp32, OUT = bf16 h/l feat.
// ============================================================================
__global__ __launch_bounds__(256) void bfgemm_ca(const float* __restrict__ img,
                                                 const __nv_bfloat16* __restrict__ Bh,
                                                 const __nv_bfloat16* __restrict__ Bl,
                                                 const float* __restrict__ bias,
                                                 __nv_bfloat16* __restrict__ Ch,
                                                 __nv_bfloat16* __restrict__ Cl, int N, int K) {
    __shared__ __align__(16) __nv_bfloat16 sAh[16 * 136], sAl[16 * 136];
    __shared__ __align__(16) __nv_bfloat16 sBh[64 * 16],  sBl[64 * 16];
    __shared__ __align__(16) float scratch[128 * 64];

    const int t = threadIdx.x;
    const int w = t >> 5;
    const int row0 = blockIdx.y << 7, col0 = blockIdx.x << 6;
    const int b = row0 >> 12, hw0 = row0 & 4095;
    const int wm = w >> 1, wn = w & 1;
    const int m0 = wm << 5, n0 = wn << 5;

    wmma::fragment<wmma::accumulator, 16, 16, 16, float> acc[2][2];
#pragma unroll
    for (int mi = 0; mi < 2; mi++)
#pragma unroll
        for (int ni = 0; ni < 2; ni++)
            wmma::fill_fragment(acc[mi][ni], 0.f);

    const uint32_t* Bh32 = (const uint32_t*)Bh;
    const uint32_t* Bl32 = (const uint32_t*)Bl;
    uint32_t* sBh32 = (uint32_t*)sBh;
    uint32_t* sBl32 = (uint32_t*)sBl;
    uint32_t* sAh32 = (uint32_t*)sAh;
    uint32_t* sAl32 = (uint32_t*)sAl;

    for (int k0 = 0; k0 < K; k0 += 16) {
#pragma unroll
        for (int i = 0; i < 2; i++) {
            int idx = t + (i << 8);
            int kk = idx >> 5, m4 = (idx & 31) << 2;
            float4 v = *(const float4*)(img + (size_t)b * 1048576 + (size_t)(k0 + kk) * 4096 + hw0 + m4);
            uint32_t h01 = bf16x2_of(v.y, v.x);
            uint32_t h23 = bf16x2_of(v.w, v.z);
            uint32_t l01 = bf16x2_of(v.y - bf16hi_f(h01), v.x - bf16lo_f(h01));
            uint32_t l23 = bf16x2_of(v.w - bf16hi_f(h23), v.z - bf16lo_f(h23));
            int so = kk * 68 + (m4 >> 1);
            sAh32[so] = h01; sAh32[so + 1] = h23;
            sAl32[so] = l01; sAl32[so + 1] = l23;
        }
#pragma unroll
        for (int i = 0; i < 2; i++) {
            int idx = t + (i << 8);
            int r = idx >> 3, c2 = idx & 7;
            size_t g = (size_t)(col0 + r) * (K >> 1) + (k0 >> 1) + c2;
            sBh32[(r << 3) + c2] = Bh32[g];
            sBl32[(r << 3) + c2] = Bl32[g];
        }
        __syncthreads();

        wmma::fragment<wmma::matrix_a, 16, 16, 16, __nv_bfloat16, wmma::col_major> ah0, ah1, al0, al1;
        wmma::fragment<wmma::matrix_b, 16, 16, 16, __nv_bfloat16, wmma::col_major> bh0, bh1, bl0, bl1;
        wmma::load_matrix_sync(ah0, sAh + m0, 136);
        wmma::load_matrix_sync(ah1, sAh + m0 + 16, 136);
        wmma::load_matrix_sync(al0, sAl + m0, 136);
        wmma::load_matrix_sync(al1, sAl + m0 + 16, 136);
        wmma::load_matrix_sync(bh0, sBh + (size_t)n0 * 16, 16);
        wmma::load_matrix_sync(bh1, sBh + (size_t)(n0 + 16) * 16, 16);
        wmma::load_matrix_sync(bl0, sBl + (size_t)n0 * 16, 16);
        wmma::load_matrix_sync(bl1, sBl + (size_t)(n0 + 16) * 16, 16);

        wmma::mma_sync(acc[0][0], ah0, bh0, acc[0][0]);
        wmma::mma_sync(acc[0][1], ah0, bh1, acc[0][1]);
        wmma::mma_sync(acc[1][0], ah1, bh0, acc[1][0]);
        wmma::mma_sync(acc[1][1], ah1, bh1, acc[1][1]);
        wmma::mma_sync(acc[0][0], ah0, bl0, acc[0][0]);
        wmma::mma_sync(acc[0][1], ah0, bl1, acc[0][1]);
        wmma::mma_sync(acc[1][0], ah1, bl0, acc[1][0]);
        wmma::mma_sync(acc[1][1], ah1, bl1, acc[1][1]);
        wmma::mma_sync(acc[0][0], al0, bh0, acc[0][0]);
        wmma::mma_sync(acc[0][1], al0, bh1, acc[0][1]);
        wmma::mma_sync(acc[1][0], al1, bh0, acc[1][0]);
        wmma::mma_sync(acc[1][1], al1, bh1, acc[1][1]);
        __syncthreads();
    }

#pragma unroll
    for (int mi = 0; mi < 2; mi++)
#pragma unroll
        for (int ni = 0; ni < 2; ni++)
            wmma::store_matrix_sync(scratch + (size_t)(m0 + mi * 16) * 64 + n0 + ni * 16,
                                    acc[mi][ni], 64, wmma::mem_row_major);
    __syncthreads();

    int r = t >> 1, cc = (t & 1) << 5;
    uint32_t* ch32 = (uint32_t*)Ch;
    uint32_t* cl32 = (uint32_t*)Cl;
#pragma unroll
    for (int q = 0; q < 8; q++) {
        float4 v = *(float4*)(scratch + r * 64 + cc + q * 4);
        float4 bb = *(const float4*)(bias + col0 + cc + q * 4);
        v.x += bb.x; v.y += bb.y; v.z += bb.z; v.w += bb.w;
        uint32_t h01 = bf16x2_of(v.y, v.x);
        uint32_t h23 = bf16x2_of(v.w, v.z);
        uint32_t l01 = bf16x2_of(v.y - bf16hi_f(h01), v.x - bf16lo_f(h01));
        uint32_t l23 = bf16x2_of(v.w - bf16hi_f(h23), v.z - bf16lo_f(h23));
        int o = (row0 + r) * (N >> 1) + ((col0 + cc) >> 1) + q * 2;
        ch32[o] = h01; ch32[o + 1] = h23;
        cl32[o] = l01; cl32[o + 1] = l23;
    }
}

// ============================================================================
// Pipelined bf16 GEMM (R6/R8 version: 128x64 block, 60KB smem, 2 CTA/SM)
// ============================================================================
#define GBF_SMEM 61440

__global__ __launch_bounds__(256) void bfgemm_bf(const __nv_bfloat16* __restrict__ Ah,
                                                 const __nv_bfloat16* __restrict__ Al,
                                                 const __nv_bfloat16* __restrict__ Bh,
                                                 const __nv_bfloat16* __restrict__ Bl,
                                                 const float* __restrict__ bias,
                                                 float* __restrict__ C, int ldc, int K,
                                                 int qcolsplit, int qrowblk) {
    extern __shared__ __align__(16) char sm[];
    const int col0 = blockIdx.x << 6;
    if (col0 < qcolsplit && (int)blockIdx.y >= qrowblk) return;

    __nv_bfloat16* sA[4];
    __nv_bfloat16* sB[4];
    uint32_t aA[4], aB[4];
#pragma unroll
    for (int i = 0; i < 4; i++) {
        sA[i] = (__nv_bfloat16*)(sm + i * 10240);
        sB[i] = (__nv_bfloat16*)(sm + 40960 + i * 5120);
        aA[i] = smem_u32(sA[i]);
        aB[i] = smem_u32(sB[i]);
    }
    float* scratch = (float*)sm;

    const int t = threadIdx.x;
    const int w = t >> 5;
    const int row0 = blockIdx.y << 7;
    const int wm = w >> 1, wn = w & 1;
    const int m0 = wm << 5, n0 = wn << 5;

    wmma::fragment<wmma::accumulator, 16, 16, 16, float> acc[2][2];
#pragma unroll
    for (int mi = 0; mi < 2; mi++)
#pragma unroll
        for (int ni = 0; ni < 2; ni++)
            wmma::fill_fragment(acc[mi][ni], 0.f);

    const int KT = K >> 5;
    auto issue = [&](int kt, int b) {
        int k0 = kt << 5;
#pragma unroll
        for (int i = 0; i < 2; i++) {
            int id = t + (i << 8);
            int r = id >> 2, k8 = (id & 3) << 3;
            uint32_t so = (uint32_t)(r * 40 + k8) << 1;
            cpa16(aA[b] + so,     Ah + (size_t)(row0 + r) * K + k0 + k8);
            cpa16(aA[b + 2] + so, Al + (size_t)(row0 + r) * K + k0 + k8);
        }
        {
            int r = t >> 2, k8 = (t & 3) << 3;
            uint32_t so = (uint32_t)(r * 40 + k8) << 1;
            cpa16(aB[b] + so,     Bh + (size_t)(col0 + r) * K + k0 + k8);
            cpa16(aB[b + 2] + so, Bl + (size_t)(col0 + r) * K + k0 + k8);
        }
        cp_commit();
    };

    issue(0, 0);
    for (int kt = 0; kt < KT; kt++) {
        int b = kt & 1;
        if (kt + 1 < KT) { issue(kt + 1, (kt + 1) & 1); cp_wait1(); }
        else cp_wait0();
        __syncthreads();
#pragma unroll
        for (int ks = 0; ks < 2; ks++) {
            wmma::fragment<wmma::matrix_a, 16, 16, 16, __nv_bfloat16, wmma::row_major> ah0, ah1, al0, al1;
            wmma::fragment<wmma::matrix_b, 16, 16, 16, __nv_bfloat16, wmma::col_major> bh0, bh1, bl0, bl1;
            wmma::load_matrix_sync(ah0, sA[b]     + (size_t)m0 * 40 + ks * 16, 40);
            wmma::load_matrix_sync(ah1, sA[b]     + (size_t)(m0 + 16) * 40 + ks * 16, 40);
            wmma::load_matrix_sync(al0, sA[b + 2] + (size_t)m0 * 40 + ks * 16, 40);
            wmma::load_matrix_sync(al1, sA[b + 2] + (size_t)(m0 + 16) * 40 + ks * 16, 40);
            wmma::load_matrix_sync(bh0, sB[b]     + (size_t)n0 * 40 + ks * 16, 40);
            wmma::load_matrix_sync(bh1, sB[b]     + (size_t)(n0 + 16) * 40 + ks * 16, 40);
            wmma::load_matrix_sync(bl0, sB[b + 2] + (size_t)n0 * 40 + ks * 16, 40);
            wmma::load_matrix_sync(bl1, sB[b + 2] + (size_t)(n0 + 16) * 40 + ks * 16, 40);

            wmma::mma_sync(acc[0][0], ah0, bh0, acc[0][0]);
            wmma::mma_sync(acc[0][1], ah0, bh1, acc[0][1]);
            wmma::mma_sync(acc[1][0], ah1, bh0, acc[1][0]);
            wmma::mma_sync(acc[1][1], ah1, bh1, acc[1][1]);
            wmma::mma_sync(acc[0][0], ah0, bl0, acc[0][0]);
            wmma::mma_sync(acc[0][1], ah0, bl1, acc[0][1]);
            wmma::mma_sync(acc[1][0], ah1, bl0, acc[1][0]);
            wmma::mma_sync(acc[1][1], ah1, bl1, acc[1][1]);
            wmma::mma_sync(acc[0][0], al0, bh0, acc[0][0]);
            wmma::mma_sync(acc[0][1], al0, bh1, acc[0][1]);
            wmma::mma_sync(acc[1][0], al1, bh0, acc[1][0]);
            wmma::mma_sync(acc[1][1], al1, bh1, acc[1][1]);
        }
        __syncthreads();
    }

#pragma unroll
    for (int mi = 0; mi < 2; mi++)
#pragma unroll
        for (int ni = 0; ni < 2; ni++)
            wmma::store_matrix_sync(scratch + (size_t)(m0 + mi * 16) * 64 + n0 + ni * 16,
                                    acc[mi][ni], 64, wmma::mem_row_major);
    __syncthreads();

    int r = t >> 1, cc = (t & 1) << 5;
#pragma unroll
    for (int q = 0; q < 8; q++) {
        float4 v = *(float4*)(scratch + r * 64 + cc + q * 4);
        float4 bb = *(const float4*)(bias + col0 + cc + q * 4);
        v.x += bb.x; v.y += bb.y; v.z += bb.z; v.w += bb.w;
        *(float4*)(C + (size_t)(row0 + r) * ldc + col0 + cc + q * 4) = v;
    }
}

// ============================================================================
// conv_out (R6/R8 version): pipelined bf16 GEMM with transposed NCHW store.
// ============================================================================
#define GTR_SMEM 61440

__global__ __launch_bounds__(256) void bfgemm_tr_bf(const __nv_bfloat16* __restrict__ Ah,
                                                    const __nv_bfloat16* __restrict__ Al,
                                                    const __nv_bfloat16* __restrict__ Bh,
                                                    const __nv_bfloat16* __restrict__ Bl,
                                                    const float* __restrict__ bias,
                                                    float* __restrict__ out, int K) {
    extern __shared__ __align__(16) char sm[];
    __nv_bfloat16* sA[4];
    __nv_bfloat16* sB[4];
    uint32_t aA[4], aB[4];
#pragma unroll
    for (int i = 0; i < 4; i++) {
        sA[i] = (__nv_bfloat16*)(sm + i * 10240);
        sB[i] = (__nv_bfloat16*)(sm + 40960 + i * 5120);
        aA[i] = smem_u32(sA[i]);
        aB[i] = smem_u32(sB[i]);
    }
    float* scratch = (float*)sm;

    const int t = threadIdx.x;
    const int w = t >> 5;
    const int row0 = blockIdx.y << 7, col0 = blockIdx.x << 6;
    const int b2 = row0 >> 12, hw0 = row0 & 4095;
    const int wm = w >> 1, wn = w & 1;
    const int m0 = wm << 5, n0 = wn << 5;

    wmma::fragment<wmma::accumulator, 16, 16, 16, float> acc[2][2];
#pragma unroll
    for (int mi = 0; mi < 2; mi++)
#pragma unroll
        for (int ni = 0; ni < 2; ni++)
            wmma::fill_fragment(acc[mi][ni], 0.f);

    const int KT = K >> 5;
    auto issue = [&](int kt, int b) {
        int k0 = kt << 5;
#pragma unroll
        for (int i = 0; i < 2; i++) {
            int id = t + (i << 8);
            int r = id >> 2, k8 = (id & 3) << 3;
            uint32_t so = (uint32_t)(r * 40 + k8) << 1;
            cpa16(aA[b] + so,     Ah + (size_t)(row0 + r) * K + k0 + k8);
            cpa16(aA[b + 2] + so, Al + (size_t)(row0 + r) * K + k0 + k8);
        }
        {
            int r = t >> 2, k8 = (t & 3) << 3;
            uint32_t so = (uint32_t)(r * 40 + k8) << 1;
            cpa16(aB[b] + so,     Bh + (size_t)(col0 + r) * K + k0 + k8);
            cpa16(aB[b + 2] + so, Bl + (size_t)(col0 + r) * K + k0 + k8);
        }
        cp_commit();
    };

    issue(0, 0);
    for (int kt = 0; kt < KT; kt++) {
        int b = kt & 1;
        if (kt + 1 < KT) { issue(kt + 1, (kt + 1) & 1); cp_wait1(); }
        else cp_wait0();
        __syncthreads();
#pragma unroll
        for (int ks = 0; ks < 2; ks++) {
            wmma::fragment<wmma::matrix_a, 16, 16, 16, __nv_bfloat16, wmma::row_major> ah0, ah1, al0, al1;
            wmma::fragment<wmma::matrix_b, 16, 16, 16, __nv_bfloat16, wmma::col_major> bh0, bh1, bl0, bl1;
            wmma::load_matrix_sync(ah0, sA[b]     + (size_t)m0 * 40 + ks * 16, 40);
            wmma::load_matrix_sync(ah1, sA[b]     + (size_t)(m0 + 16) * 40 + ks * 16, 40);
            wmma::load_matrix_sync(al0, sA[b + 2] + (size_t)m0 * 40 + ks * 16, 40);
            wmma::load_matrix_sync(al1, sA[b + 2] + (size_t)(m0 + 16) * 40 + ks * 16, 40);
            wmma::load_matrix_sync(bh0, sB[b]     + (size_t)n0 * 40 + ks * 16, 40);
            wmma::load_matrix_sync(bh1, sB[b]     + (size_t)(n0 + 16) * 40 + ks * 16, 40);
            wmma::load_matrix_sync(bl0, sB[b + 2] + (size_t)n0 * 40 + ks * 16, 40);
            wmma::load_matrix_sync(bl1, sB[b + 2] + (size_t)(n0 + 16) * 40 + ks * 16, 40);

            wmma::mma_sync(acc[0][0], ah0, bh0, acc[0][0]);
            wmma::mma_sync(acc[0][1], ah0, bh1, acc[0][1]);
            wmma::mma_sync(acc[1][0], ah1, bh0, acc[1][0]);
            wmma::mma_sync(acc[1][1], ah1, bh1, acc[1][1]);
            wmma::mma_sync(acc[0][0], ah0, bl0, acc[0][0]);
            wmma::mma_sync(acc[0][1], ah0, bl1, acc[0][1]);
            wmma::mma_sync(acc[1][0], ah1, bl0, acc[1][0]);
            wmma::mma_sync(acc[1][1], ah1, bl1, acc[1][1]);
            wmma::mma_sync(acc[0][0], al0, bh0, acc[0][0]);
            wmma::mma_sync(acc[0][1], al0, bh1, acc[0][1]);
            wmma::mma_sync(acc[1][0], al1, bh0, acc[1][0]);
            wmma::mma_sync(acc[1][1], al1, bh1, acc[1][1]);
        }
        __syncthreads();
    }

#pragma unroll
    for (int mi = 0; mi < 2; mi++)
#pragma unroll
        for (int ni = 0; ni < 2; ni++)
            wmma::store_matrix_sync(scratch + (size_t)(n0 + ni * 16) * 132 + m0 + mi * 16,
                                    acc[mi][ni], 132, wmma::mem_col_major);
    __syncthreads();

    const int lane = t & 31;
#pragma unroll
    for (int nn = 0; nn < 8; nn++) {
        int n = (w << 3) + nn;
        float bv = bias[col0 + n];
        float* orow = out + (size_t)b2 * 1048576 + (size_t)(col0 + n) * 4096 + hw0;
#pragma unroll
        for (int it = 0; it < 4; it++) {
            int m = (it << 5) + lane;
            orow[m] = scratch[n * 132 + m] + bv;
        }
    }
}

// ============================================================================
// Windowed attention, 4-way key-split (R8 version)
// ============================================================================
#define ATTN_SMEM 52224

__global__ __launch_bounds__(256) void attn_kernel(const float* __restrict__ qkv,
                                                   __nv_bfloat16* __restrict__ Oh,
                                                   __nv_bfloat16* __restrict__ Ol) {
    extern __shared__ __align__(16) char asmem[];
    float4 (*sK)[4] = (float4(*)[4])asmem;
    float4 (*sV)[4] = (float4(*)[4])(asmem + 16384);
    float* pm = (float*)(asmem + 32768);
    float* pl = (float*)(asmem + 33792);
    float* po = (float*)(asmem + 34816);

    const int h = blockIdx.x, w = blockIdx.y;
    const int t = threadIdx.x;
    const int sg = t >> 6, q = t & 63;
    const int T = g_win_cnt[w];
    const int* wt = &g_win_tok[w * CAP];

    for (int j = t; j < T; j += 256) {
        int tok = wt[j];
        const float4* kp = (const float4*)(qkv + (size_t)tok * 384 + 128 + h * 16);
        const float4* vp = (const float4*)(qkv + (size_t)tok * 384 + 256 + h * 16);
        sK[j][0] = kp[0]; sK[j][1] = kp[1]; sK[j][2] = kp[2]; sK[j][3] = kp[3];
        sV[j][0] = vp[0]; sV[j][1] = vp[1]; sV[j][2] = vp[2]; sV[j][3] = vp[3];
    }
    __syncthreads();

    const int qtok = wt[q];
    const float4* qp = (const float4*)(qkv + (size_t)qtok * 384 + h * 16);
    float4 q0 = qp[0], q1 = qp[1], q2 = qp[2], q3 = qp[3];

    const int j0 = (T * sg) >> 2, j1 = (T * (sg + 1)) >> 2;
    float m = -1e30f, l = 0.f;
    float4 o0 = {0,0,0,0}, o1 = {0,0,0,0}, o2 = {0,0,0,0}, o3 = {0,0,0,0};
    for (int j = j0; j < j1; j++) {
        float4 k0 = sK[j][0], k1 = sK[j][1], k2 = sK[j][2], k3 = sK[j][3];
        float s = q0.x*k0.x + q0.y*k0.y + q0.z*k0.z + q0.w*k0.w
                + q1.x*k1.x + q1.y*k1.y + q1.z*k1.z + q1.w*k1.w
                + q2.x*k2.x + q2.y*k2.y + q2.z*k2.z + q2.w*k2.w
                + q3.x*k3.x + q3.y*k3.y + q3.z*k3.z + q3.w*k3.w;
        s *= 0.25f;
        float mn = fmaxf(m, s);
        float sc = __expf(m - mn);
        float p  = __expf(s - mn);
        l = l * sc + p;
        float4 v0 = sV[j][0], v1 = sV[j][1], v2 = sV[j][2], v3 = sV[j][3];
        o0.x = o0.x*sc + p*v0.x; o0.y = o0.y*sc + p*v0.y; o0.z = o0.z*sc + p*v0.z; o0.w = o0.w*sc + p*v0.w;
        o1.x = o1.x*sc + p*v1.x; o1.y = o1.y*sc + p*v1.y; o1.z = o1.z*sc + p*v1.z; o1.w = o1.w*sc + p*v1.w;
        o2.x = o2.x*sc + p*v2.x; o2.y = o2.y*sc + p*v2.y; o2.z = o2.z*sc + p*v2.z; o2.w = o2.w*sc + p*v2.w;
        o3.x = o3.x*sc + p*v3.x; o3.y = o3.y*sc + p*v3.y; o3.z = o3.z*sc + p*v3.z; o3.w = o3.w*sc + p*v3.w;
        m = mn;
    }
    pm[t] = m;
    pl[t] = l;
    float* pop = po + (sg * 64 + q) * 17;
    pop[0] = o0.x; pop[1] = o0.y; pop[2]  = o0.z; pop[3]  = o0.w;
    pop[4] = o1.x; pop[5] = o1.y; pop[6]  = o1.z; pop[7]  = o1.w;
    pop[8] = o2.x; pop[9] = o2.y; pop[10] = o2.z; pop[11] = o2.w;
    pop[12] = o3.x; pop[13] = o3.y; pop[14] = o3.z; pop[15] = o3.w;
    __syncthreads();

    if (t < 64) {
        float m0 = pm[q], m1 = pm[64 + q], m2 = pm[128 + q], m3 = pm[192 + q];
        float mm = fmaxf(fmaxf(m0, m1), fmaxf(m2, m3));
        float e0 = __expf(m0 - mm), e1 = __expf(m1 - mm);
        float e2 = __expf(m2 - mm), e3 = __expf(m3 - mm);
        float lt = pl[q] * e0 + pl[64 + q] * e1 + pl[128 + q] * e2 + pl[192 + q] * e3;
        float inv = 1.f / lt;
        const float* p0 = po + q * 17;
        const float* p1 = po + (64 + q) * 17;
        const float* p2 = po + (128 + q) * 17;
        const float* p3 = po + (192 + q) * 17;
        uint32_t* oh32 = (uint32_t*)Oh;
        uint32_t* ol32 = (uint32_t*)Ol;
        int ob = qtok * 64 + h * 8;
#pragma unroll
        for (int j = 0; j < 8; j++) {
            float vlo = (p0[2*j]   * e0 + p1[2*j]   * e1 + p2[2*j]   * e2 + p3[2*j]   * e3) * inv;
            float vhi = (p0[2*j+1] * e0 + p1[2*j+1] * e1 + p2[2*j+1] * e2 + p3[2*j+1] * e3) * inv;
            uint32_t hh = bf16x2_of(vhi, vlo);
            oh32[ob + j] = hh;
            ol32[ob + j] = bf16x2_of(vhi - bf16hi_f(hh), vlo - bf16lo_f(hh));
        }
    }
}

// ============================================================================
// Fused proj + RK4 ODE on raw mma.sync (m16n8k16): RK4 state lives in
// registers at accumulator positions; no fp32 scratch round-trip.
// 128 CTAs x 256 thr; CTA owns 64 rows; warps 2m x 4n, warp tile 32x32.
// SMEM: [0) bias 512 | [512) Wh 34816 | [35328) Wl | [70144) Zh 17408 |
//       [87552) Zl | [104960) PWh (->sImg fp32 after proj) | [139776) PWl
// ============================================================================
#define ODE_SMEM 174592

__global__ __launch_bounds__(256, 1) void ode_mma(const __nv_bfloat16* __restrict__ Oh,
                                                  const __nv_bfloat16* __restrict__ Ol,
                                                  const __nv_bfloat16* __restrict__ PWh,
                                                  const __nv_bfloat16* __restrict__ PWl,
                                                  const float* __restrict__ pbias,
                                                  const __nv_bfloat16* __restrict__ Wh_g,
                                                  const __nv_bfloat16* __restrict__ Wl_g,
                                                  const float* __restrict__ bias,
                                                  __nv_bfloat16* __restrict__ Rh,
                                                  __nv_bfloat16* __restrict__ Rl) {
    extern __shared__ __align__(16) char sm[];
    float* sBias = (float*)sm;
    char* sWh  = sm + 512;
    char* sWl  = sm + 35328;
    char* sZh  = sm + 70144;
    char* sZl  = sm + 87552;
    char* sPWh = sm + 104960;
    char* sPWl = sm + 139776;
    float* sImg = (float*)(sm + 104960);   // aliases PWh after proj

    const int t = threadIdx.x;
    const int lane = t & 31;
    const int wid = t >> 5;
    const int wm = wid >> 2, wn = wid & 3;
    const int m0 = wm << 5, n0 = wn << 5;
    const int row0 = blockIdx.x << 6;

    // ---- fill smem: W/PW (pitch 68 u32), bias, o -> Z ----
    {
        const uint32_t* wh32 = (const uint32_t*)Wh_g;
        const uint32_t* wl32 = (const uint32_t*)Wl_g;
        const uint32_t* ph32 = (const uint32_t*)PWh;
        const uint32_t* pl32 = (const uint32_t*)PWl;
        uint32_t* dWh = (uint32_t*)sWh;
        uint32_t* dWl = (uint32_t*)sWl;
        uint32_t* dPh = (uint32_t*)sPWh;
        uint32_t* dPl = (uint32_t*)sPWl;
        for (int idx = t; idx < 8192; idx += 256) {
            int n = idx >> 6, c2 = idx & 63;
            dWh[n * 68 + c2] = wh32[idx];
            dWl[n * 68 + c2] = wl32[idx];
            dPh[n * 68 + c2] = ph32[idx];
            dPl[n * 68 + c2] = pl32[idx];
        }
        const uint32_t* oh32 = (const uint32_t*)Oh + (size_t)row0 * 64;
        const uint32_t* ol32 = (const uint32_t*)Ol + (size_t)row0 * 64;
        uint32_t* zh = (uint32_t*)sZh;
        uint32_t* zl = (uint32_t*)sZl;
        for (int idx = t; idx < 4096; idx += 256) {
            int n = idx >> 6, c2 = idx & 63;
            zh[n * 68 + c2] = oh32[idx];
            zl[n * 68 + c2] = ol32[idx];
        }
        if (t < 128) sBias[t] = bias[t];
    }
    __syncthreads();

    // ---- ldmatrix address offsets (bytes, relative to matrix base) ----
    const int g3 = lane >> 3, r8 = lane & 7;
    uint32_t aOff[2], bOff[2];
#pragma unroll
    for (int mf = 0; mf < 2; mf++)
        aOff[mf] = (uint32_t)((m0 + mf * 16 + (g3 & 1) * 8 + r8) * 136) * 2 + (g3 >> 1) * 16;
#pragma unroll
    for (int nt = 0; nt < 2; nt++)
        bOff[nt] = (uint32_t)((n0 + nt * 16 + (g3 >> 1) * 8 + r8) * 136) * 2 + (g3 & 1) * 16;

    const uint32_t zhB = smem_u32(sZh), zlB = smem_u32(sZl);
    const uint32_t whB = smem_u32(sWh), wlB = smem_u32(sWl);
    const uint32_t phB = smem_u32(sPWh), plB = smem_u32(sPWl);

    // element ownership
    const int gr = lane >> 2, q2 = (lane & 3) << 1;
    float bias2[4][2];
#pragma unroll
    for (int nj = 0; nj < 4; nj++) {
        bias2[nj][0] = sBias[n0 + nj * 8 + q2];
        bias2[nj][1] = sBias[n0 + nj * 8 + q2 + 1];
    }

    float d[2][4][4], y[2][4][4], accv[2][4][4];

    // ---- 3-pass hi/lo MMA phase macro: d += Ah*Bh + Ah*Bl + Al*Bh ----
#define MMA_PHASE(AH, AL, BH, BL)                                                  \
    _Pragma("unroll")                                                              \
    for (int kk = 0; kk < 8; kk++) {                                               \
        uint32_t ko = kk * 32;                                                     \
        uint32_t ah0[4], ah1[4], al0[4], al1[4];                                   \
        uint32_t bh0[4], bh1[4], bl0[4], bl1[4];                                   \
        ldm4(ah0, (AH) + aOff[0] + ko); ldm4(ah1, (AH) + aOff[1] + ko);            \
        ldm4(al0, (AL) + aOff[0] + ko); ldm4(al1, (AL) + aOff[1] + ko);            \
        ldm4(bh0, (BH) + bOff[0] + ko); ldm4(bh1, (BH) + bOff[1] + ko);            \
        ldm4(bl0, (BL) + bOff[0] + ko); ldm4(bl1, (BL) + bOff[1] + ko);            \
        _Pragma("unroll")                                                          \
        for (int nj = 0; nj < 4; nj++) {                                           \
            const uint32_t* bhp = (nj < 2) ? bh0 : bh1;                            \
            const uint32_t* blp = (nj < 2) ? bl0 : bl1;                            \
            uint32_t bh_0 = bhp[(nj & 1) * 2], bh_1 = bhp[(nj & 1) * 2 + 1];       \
            uint32_t bl_0 = blp[(nj & 1) * 2], bl_1 = blp[(nj & 1) * 2 + 1];       \
            mma16816(d[0][nj], ah0, bh_0, bh_1);                                   \
            mma16816(d[1][nj], ah1, bh_0, bh_1);                                   \
            mma16816(d[0][nj], al0, bh_0, bh_1);                                   \
            mma16816(d[1][nj], al1, bh_0, bh_1);                                   \
            mma16816(d[0][nj], ah0, bl_0, bl_1);                                   \
            mma16816(d[1][nj], ah1, bl_0, bl_1);                                   \
        }                                                                          \
    }

    // ---- proj: img = o @ Wpr^T + bpr ----
#pragma unroll
    for (int mf = 0; mf < 2; mf++)
#pragma unroll
        for (int nj = 0; nj < 4; nj++)
#pragma unroll
            for (int i = 0; i < 4; i++) d[mf][nj][i] = 0.f;
    MMA_PHASE(zhB, zlB, phB, plB)
    __syncthreads();   // protect PW reads before sImg alias writes

#pragma unroll
    for (int mf = 0; mf < 2; mf++) {
#pragma unroll
        for (int nj = 0; nj < 4; nj++) {
            const int c = n0 + nj * 8 + q2;
            float pb0 = pbias[c], pb1 = pbias[c + 1];
#pragma unroll
            for (int hh = 0; hh < 2; hh++) {
                const int row = m0 + mf * 16 + gr + hh * 8;
                float z0 = d[mf][nj][hh * 2]     + pb0;
                float z1 = d[mf][nj][hh * 2 + 1] + pb1;
                y[mf][nj][hh * 2] = z0; y[mf][nj][hh * 2 + 1] = z1;
                *(float2*)(sImg + row * 128 + c) = make_float2(z0, z1);
                uint32_t hz = bf16x2_of(z1, z0);
                *(uint32_t*)(sZh + (row * 136 + c) * 2) = hz;
                *(uint32_t*)(sZl + (row * 136 + c) * 2) =
                    bf16x2_of(z1 - bf16hi_f(hz), z0 - bf16lo_f(hz));
            }
        }
    }
    __syncthreads();

    // ---- 16 RK4 evaluations ----
    for (int ev = 0; ev < 16; ev++) {
#pragma unroll
        for (int mf = 0; mf < 2; mf++)
#pragma unroll
            for (int nj = 0; nj < 4; nj++)
#pragma unroll
                for (int i = 0; i < 4; i++) d[mf][nj][i] = 0.f;
        MMA_PHASE(zhB, zlB, whB, wlB)
        __syncthreads();   // other warps still reading Z rows

        const int st = ev & 3;
        const float zc = (st < 2) ? 0.125f : 0.25f;
        const float aw = (st == 1 || st == 2) ? 2.f : 1.f;
#pragma unroll
        for (int mf = 0; mf < 2; mf++) {
#pragma unroll
            for (int nj = 0; nj < 4; nj++) {
                const int c = n0 + nj * 8 + q2;
#pragma unroll
                for (int hh = 0; hh < 2; hh++) {
                    const int row = m0 + mf * 16 + gr + hh * 8;
                    float kf0 = fmaxf(d[mf][nj][hh * 2]     + bias2[nj][0], 0.f);
                    float kf1 = fmaxf(d[mf][nj][hh * 2 + 1] + bias2[nj][1], 0.f);
                    float a0 = (st == 0) ? kf0 : accv[mf][nj][hh * 2]     + aw * kf0;
                    float a1 = (st == 0) ? kf1 : accv[mf][nj][hh * 2 + 1] + aw * kf1;
                    accv[mf][nj][hh * 2] = a0; accv[mf][nj][hh * 2 + 1] = a1;
                    float z0, z1;
                    if (st < 3) {
                        z0 = y[mf][nj][hh * 2]     + zc * kf0;
                        z1 = y[mf][nj][hh * 2 + 1] + zc * kf1;
                    } else {
                        y[mf][nj][hh * 2]     += (1.f / 24.f) * a0;
                        y[mf][nj][hh * 2 + 1] += (1.f / 24.f) * a1;
                        z0 = y[mf][nj][hh * 2]; z1 = y[mf][nj][hh * 2 + 1];
                    }
                    uint32_t hz = bf16x2_of(z1, z0);
                    *(uint32_t*)(sZh + (row * 136 + c) * 2) = hz;
                    *(uint32_t*)(sZl + (row * 136 + c) * 2) =
                        bf16x2_of(z1 - bf16hi_f(hz), z0 - bf16lo_f(hz));
                }
            }
        }
        __syncthreads();
    }

    // ---- res = y_final + img, emit bf16 h/l ----
    uint32_t* rh32 = (uint32_t*)Rh;
    uint32_t* rl32 = (uint32_t*)Rl;
#pragma unroll
    for (int mf = 0; mf < 2; mf++) {
#pragma unroll
        for (int nj = 0; nj < 4; nj++) {
            const int c = n0 + nj * 8 + q2;
#pragma unroll
            for (int hh = 0; hh < 2; hh++) {
                const int row = m0 + mf * 16 + gr + hh * 8;
                float2 iv = *(const float2*)(sImg + row * 128 + c);
                float r0 = y[mf][nj][hh * 2]     + iv.x;
                float r1 = y[mf][nj][hh * 2 + 1] + iv.y;
                uint32_t hz = bf16x2_of(r1, r0);
                int o = (row0 + row) * 64 + (c >> 1);
                rh32[o] = hz;
                rl32[o] = bf16x2_of(r1 - bf16hi_f(hz), r0 - bf16lo_f(hz));
            }
        }
    }
#undef MMA_PHASE
}

// ---------------- launch ----------------
extern "C" void kernel_launch(void* const* d_in, const int* in_sizes, int n_in,
                              void* d_out, int out_size) {
    const float* img   = (const float*)d_in[0];
    const int*   ptsuv = (const int*)  d_in[1];
    const float* ptsf  = (const float*)d_in[2];
    const float* wci   = (const float*)d_in[3];
    const float* bci   = (const float*)d_in[4];
    const float* wqkv  = (const float*)d_in[5];
    const float* bqkv  = (const float*)d_in[6];
    const float* wpr   = (const float*)d_in[7];
    const float* bpr   = (const float*)d_in[8];
    const float* wode  = (const float*)d_in[9];
    const float* bode  = (const float*)d_in[10];
    const float* wco   = (const float*)d_in[11];
    const float* bco   = (const float*)d_in[12];
    float* out = (float*)d_out;

    float *pqkv;
    __nv_bfloat16 *pwh, *pwl, *pfh, *pfl, *poh, *pol, *prh, *prl;
    cudaGetSymbolAddress((void**)&pqkv, g_qkv);
    cudaGetSymbolAddress((void**)&pwh,  g_wh);
    cudaGetSymbolAddress((void**)&pwl,  g_wl);
    cudaGetSymbolAddress((void**)&pfh,  g_feath);
    cudaGetSymbolAddress((void**)&pfl,  g_featl);
    cudaGetSymbolAddress((void**)&poh,  g_oh);
    cudaGetSymbolAddress((void**)&pol,  g_ol);
    cudaGetSymbolAddress((void**)&prh,  g_resh);
    cudaGetSymbolAddress((void**)&prl,  g_resl);

    cudaFuncSetAttribute(ode_mma,      cudaFuncAttributeMaxDynamicSharedMemorySize, ODE_SMEM);
    cudaFuncSetAttribute(bfgemm_bf,    cudaFuncAttributeMaxDynamicSharedMemorySize, GBF_SMEM);
    cudaFuncSetAttribute(bfgemm_tr_bf, cudaFuncAttributeMaxDynamicSharedMemorySize, GTR_SMEM);
    cudaFuncSetAttribute(attn_kernel,  cudaFuncAttributeMaxDynamicSharedMemorySize, ATTN_SMEM);

    prep<<<1632, 256>>>(wci, wqkv, wpr, wode, wco, ptsf, ptsuv);
    pt_scatter<<<NCHUNK, 256>>>();
    // conv_in from NCHW -> feat h/l
    bfgemm_ca<<<dim3(2, 64), 256>>>(img, pwh + WOFF_CI, pwl + WOFF_CI, bci, pfh, pfl, 128, 256);
    // qkv merged: Q (cols<128) only for pixel rows (by<64)
    bfgemm_bf<<<dim3(6, 128), 256, GBF_SMEM>>>(pfh, pfl, pwh + WOFF_QKV, pwl + WOFF_QKV,
                                               bqkv, pqkv, 384, 128, 128, 64);
    // attention (4-way key split) -> o h/l
    attn_kernel<<<dim3(8, 128), 256, ATTN_SMEM>>>(pqkv, poh, pol);
    // fused proj + RK4 ODE on mma.sync -> res h/l
    ode_mma<<<128, 256, ODE_SMEM>>>(poh, pol, pwh + WOFF_PR, pwl + WOFF_PR, bpr,
                                    pwh + WOFF_ODE, pwl + WOFF_ODE, bode, prh, prl);
    // conv_out -> NCHW out
    bfgemm_tr_bf<<<dim3(4, 64), 256, GTR_SMEM>>>(prh, prl, pwh + WOFF_CO, pwl + WOFF_CO,
                                                 bco, out, 128);
}

// round 11
// speedup vs baseline: 1.6051x; 1.0573x over previous
#include <cuda_runtime.h>
#include <cuda_bf16.h>
#include <mma.h>
#include <cstdint>

using namespace nvcuda;

#define NPIX 8192
#define NPTS 8192
#define NTOK 16384
#define NWIN 128
#define CAP  256
#define NCHUNK 32

// ---------------- scratch (device globals; no allocation) ----------------
__device__ __nv_bfloat16 g_imgh[2097152], g_imgl[2097152];
__device__ __nv_bfloat16 g_feath[NTOK * 128], g_featl[NTOK * 128];
__device__ float g_qkv [NTOK * 384];
__device__ __nv_bfloat16 g_oh[NPIX * 128], g_ol[NPIX * 128];
__device__ __nv_bfloat16 g_resh[NPIX * 128], g_resl[NPIX * 128];
__device__ __nv_bfloat16 g_wh[147456];
__device__ __nv_bfloat16 g_wl[147456];
__device__ int   g_ptw [NPTS];
__device__ int   g_hist[NCHUNK * NWIN];
__device__ int   g_win_tok[NWIN * CAP];
__device__ int   g_win_cnt[NWIN];

#define WOFF_CI  0
#define WOFF_QKV 32768
#define WOFF_PR  81920
#define WOFF_ODE 98304
#define WOFF_CO  114688

// ---------------- helpers ----------------
__device__ __forceinline__ uint32_t bf16x2_of(float hi, float lo) {
    uint32_t r; asm("cvt.rn.bf16x2.f32 %0, %1, %2;" : "=r"(r) : "f"(hi), "f"(lo)); return r;
}
__device__ __forceinline__ float bf16lo_f(uint32_t v) { return __uint_as_float(v << 16); }
__device__ __forceinline__ float bf16hi_f(uint32_t v) { return __uint_as_float(v & 0xffff0000u); }

__device__ __forceinline__ uint32_t smem_u32(const void* p) {
    uint32_t a;
    asm("{ .reg .u64 t; cvta.to.shared.u64 t, %1; cvt.u32.u64 %0, t; }" : "=r"(a) : "l"(p));
    return a;
}
__device__ __forceinline__ void cpa16(uint32_t s, const void* g) {
    asm volatile("cp.async.cg.shared.global [%0], [%1], 16;" :: "r"(s), "l"(g));
}
__device__ __forceinline__ void cp_commit() { asm volatile("cp.async.commit_group;" ::: "memory"); }
__device__ __forceinline__ void cp_wait1() { asm volatile("cp.async.wait_group 1;" ::: "memory"); }
__device__ __forceinline__ void cp_wait0() { asm volatile("cp.async.wait_group 0;" ::: "memory"); }

__device__ __forceinline__ void ldm4(uint32_t* r, uint32_t addr) {
    asm volatile("ldmatrix.sync.aligned.m8n8.x4.shared.b16 {%0,%1,%2,%3}, [%4];"
                 : "=r"(r[0]), "=r"(r[1]), "=r"(r[2]), "=r"(r[3]) : "r"(addr));
}
__device__ __forceinline__ void mma16816(float* d, const uint32_t* a, uint32_t b0, uint32_t b1) {
    asm volatile("mma.sync.aligned.m16n8k16.row.col.f32.bf16.bf16.f32 "
                 "{%0,%1,%2,%3}, {%4,%5,%6,%7}, {%8,%9}, {%0,%1,%2,%3};"
                 : "+f"(d[0]), "+f"(d[1]), "+f"(d[2]), "+f"(d[3])
                 : "r"(a[0]), "r"(a[1]), "r"(a[2]), "r"(a[3]), "r"(b0), "r"(b1));
}

// ============================================================================
// Merged prep: weights | points | wid/hist/pixel slots | image split
// ============================================================================
__global__ void prep(const float* __restrict__ wci, const float* __restrict__ wqkv,
                     const float* __restrict__ wpr, const float* __restrict__ wode,
                     const float* __restrict__ wco, const float* __restrict__ ptsf,
                     const int* __restrict__ uv, const float* __restrict__ img) {
    __shared__ int cnt[NWIN];
    int bid = blockIdx.x, t = threadIdx.x;
    if (bid < 576) {
        int i = bid * 256 + t;
        if (i >= 147456) return;
        float x;
        if (i < WOFF_QKV)      x = wci [i];
        else if (i < WOFF_PR)  x = wqkv[i - WOFF_QKV];
        else if (i < WOFF_ODE) x = wpr [i - WOFF_PR];
        else if (i < WOFF_CO)  x = wode[i - WOFF_ODE];
        else                   x = wco [i - WOFF_CO];
        __nv_bfloat16 h = __float2bfloat16(x);
        g_wh[i] = h;
        g_wl[i] = __float2bfloat16(x - __bfloat162float(h));
    } else if (bid < 1600) {
        int i = (bid - 576) * 256 + t;
        float4 v = ((const float4*)ptsf)[i];
        uint32_t h0 = bf16x2_of(v.y, v.x);
        uint32_t h1 = bf16x2_of(v.w, v.z);
        uint32_t l0 = bf16x2_of(v.y - bf16hi_f(h0), v.x - bf16lo_f(h0));
        uint32_t l1 = bf16x2_of(v.w - bf16hi_f(h1), v.z - bf16lo_f(h1));
        uint32_t* fh = (uint32_t*)g_feath;
        uint32_t* fl = (uint32_t*)g_featl;
        int o = 524288 + 2 * i;
        fh[o] = h0; fh[o + 1] = h1;
        fl[o] = l0; fl[o + 1] = l1;
    } else if (bid < 1632) {
        int c = bid - 1600;
        int i = c * 256 + t;
        if (t < NWIN) cnt[t] = 0;
        __syncthreads();
        int b = uv[3 * i] & 1;
        int u = uv[3 * i + 1] & 63;
        int v = uv[3 * i + 2] & 63;
        int wid = ((b * 8 + (v >> 3)) << 3) + (u >> 3);
        g_ptw[i] = wid;
        atomicAdd(&cnt[wid], 1);
        {
            int w = i >> 6, r = i & 63;
            int wb = w >> 6, wy = (w >> 3) & 7, wx = w & 7;
            int pv = wy * 8 + (r >> 3), pu = wx * 8 + (r & 7);
            g_win_tok[w * CAP + r] = wb * 4096 + pv * 64 + pu;
        }
        __syncthreads();
        if (t < NWIN) g_hist[c * NWIN + t] = cnt[t];
    } else {
        int i = (bid - 1632) * 256 + t;
        float4 v = ((const float4*)img)[i];
        uint32_t h0 = bf16x2_of(v.y, v.x);
        uint32_t h1 = bf16x2_of(v.w, v.z);
        uint32_t l0 = bf16x2_of(v.y - bf16hi_f(h0), v.x - bf16lo_f(h0));
        uint32_t l1 = bf16x2_of(v.w - bf16hi_f(h1), v.z - bf16lo_f(h1));
        uint32_t* ih = (uint32_t*)g_imgh;
        uint32_t* il = (uint32_t*)g_imgl;
        int o = 2 * i;
        ih[o] = h0; ih[o + 1] = h1;
        il[o] = l0; il[o + 1] = l1;
    }
}

// ---------------- scatter with inline cross-chunk scan ----------------
__global__ void pt_scatter() {
    __shared__ int cnt[NWIN];
    int t = threadIdx.x;
    int lane = t & 31;
    int c = blockIdx.x;
    int i = c * 256 + t;
    if (t < NWIN) {
        int run = 0;
        for (int cc = 0; cc < c; cc++) run += g_hist[cc * NWIN + t];
        cnt[t] = run;
        if (c == NCHUNK - 1) {
            int tot = 64 + run + g_hist[(NCHUNK - 1) * NWIN + t];
            g_win_cnt[t] = tot < CAP ? tot : CAP;
        }
    }
    __syncthreads();
    int wid = g_ptw[i];
    for (int wv = 0; wv < 8; wv++) {
        if ((t >> 5) == wv) {
            unsigned mask = __match_any_sync(0xffffffffu, wid);
            int prior = __popc(mask & ((1u << lane) - 1u));
            int base = cnt[wid];
            __syncwarp();
            int rank = 64 + base + prior;
            if (rank < CAP) g_win_tok[wid * CAP + rank] = NPIX + i;
            if (prior == 0) cnt[wid] = base + __popc(mask);
        }
        __syncthreads();
    }
}

// ============================================================================
// conv_in: 3-stage pipelined bf16 GEMM, A col-major from split NCHW image.
// ============================================================================
#define CA_SMEM 82944

__global__ __launch_bounds__(256) void wgemm_ca3(const __nv_bfloat16* __restrict__ Ah,
                                                 const __nv_bfloat16* __restrict__ Al,
                                                 const __nv_bfloat16* __restrict__ Bh,
                                                 const __nv_bfloat16* __restrict__ Bl,
                                                 const float* __restrict__ bias,
                                                 __nv_bfloat16* __restrict__ Ch,
                                                 __nv_bfloat16* __restrict__ Cl, int N, int K) {
    extern __shared__ __align__(16) char sm[];
    const uint32_t smb = smem_u32(sm);
    const int t = threadIdx.x;
    const int w = t >> 5;
    const int row0 = blockIdx.y << 7, col0 = blockIdx.x << 6;
    const int b = row0 >> 12, hw0 = row0 & 4095;
    const int m0 = (w >> 1) << 5, n0 = (w & 1) << 5;
    const int KT = K >> 5;

    auto issue = [&](int kt, int stg) {
        int k0 = kt << 5;
        uint32_t sb = smb + (uint32_t)stg * 27648;
#pragma unroll
        for (int i = 0; i < 2; i++) {
            int id = t + (i << 8);
            int kk = id >> 4, m8 = (id & 15) << 3;
            uint32_t so = (uint32_t)(kk * 136 + m8) << 1;
            size_t g = (size_t)b * 1048576 + (size_t)(k0 + kk) * 4096 + hw0 + m8;
            cpa16(sb + so,        Ah + g);
            cpa16(sb + 8704 + so, Al + g);
        }
        {
            int r = t >> 2, k8 = (t & 3) << 3;
            uint32_t so = (uint32_t)(r * 40 + k8) << 1;
            cpa16(sb + 17408 + so, Bh + (size_t)(col0 + r) * K + k0 + k8);
            cpa16(sb + 22528 + so, Bl + (size_t)(col0 + r) * K + k0 + k8);
        }
        cp_commit();
    };

    wmma::fragment<wmma::accumulator, 16, 16, 16, float> acc[2][2];
#pragma unroll
    for (int mi = 0; mi < 2; mi++)
#pragma unroll
        for (int ni = 0; ni < 2; ni++)
            wmma::fill_fragment(acc[mi][ni], 0.f);

    issue(0, 0);
    issue(1, 1);
    for (int kt = 0; kt < KT; kt++) {
        if (kt + 1 < KT) cp_wait1(); else cp_wait0();
        __syncthreads();
        if (kt + 2 < KT) issue(kt + 2, (kt + 2) % 3);
        char* sb = sm + (kt % 3) * 27648;
        __nv_bfloat16* sAh = (__nv_bfloat16*)sb;
        __nv_bfloat16* sAl = (__nv_bfloat16*)(sb + 8704);
        __nv_bfloat16* sBh = (__nv_bfloat16*)(sb + 17408);
        __nv_bfloat16* sBl = (__nv_bfloat16*)(sb + 22528);
#pragma unroll
        for (int ks = 0; ks < 2; ks++) {
            wmma::fragment<wmma::matrix_a, 16, 16, 16, __nv_bfloat16, wmma::col_major> ah0, ah1, al0, al1;
            wmma::fragment<wmma::matrix_b, 16, 16, 16, __nv_bfloat16, wmma::col_major> bh0, bh1, bl0, bl1;
            wmma::load_matrix_sync(ah0, sAh + (size_t)ks * 16 * 136 + m0, 136);
            wmma::load_matrix_sync(ah1, sAh + (size_t)ks * 16 * 136 + m0 + 16, 136);
            wmma::load_matrix_sync(al0, sAl + (size_t)ks * 16 * 136 + m0, 136);
            wmma::load_matrix_sync(al1, sAl + (size_t)ks * 16 * 136 + m0 + 16, 136);
            wmma::load_matrix_sync(bh0, sBh + (size_t)n0 * 40 + ks * 16, 40);
            wmma::load_matrix_sync(bh1, sBh + (size_t)(n0 + 16) * 40 + ks * 16, 40);
            wmma::load_matrix_sync(bl0, sBl + (size_t)n0 * 40 + ks * 16, 40);
            wmma::load_matrix_sync(bl1, sBl + (size_t)(n0 + 16) * 40 + ks * 16, 40);

            wmma::mma_sync(acc[0][0], ah0, bh0, acc[0][0]);
            wmma::mma_sync(acc[0][1], ah0, bh1, acc[0][1]);
            wmma::mma_sync(acc[1][0], ah1, bh0, acc[1][0]);
            wmma::mma_sync(acc[1][1], ah1, bh1, acc[1][1]);
            wmma::mma_sync(acc[0][0], ah0, bl0, acc[0][0]);
            wmma::mma_sync(acc[0][1], ah0, bl1, acc[0][1]);
            wmma::mma_sync(acc[1][0], ah1, bl0, acc[1][0]);
            wmma::mma_sync(acc[1][1], ah1, bl1, acc[1][1]);
            wmma::mma_sync(acc[0][0], al0, bh0, acc[0][0]);
            wmma::mma_sync(acc[0][1], al0, bh1, acc[0][1]);
            wmma::mma_sync(acc[1][0], al1, bh0, acc[1][0]);
            wmma::mma_sync(acc[1][1], al1, bh1, acc[1][1]);
        }
    }
    __syncthreads();

    float* scratch = (float*)sm;
#pragma unroll
    for (int mi = 0; mi < 2; mi++)
#pragma unroll
        for (int ni = 0; ni < 2; ni++)
            wmma::store_matrix_sync(scratch + (size_t)(m0 + mi * 16) * 64 + n0 + ni * 16,
                                    acc[mi][ni], 64, wmma::mem_row_major);
    __syncthreads();

    int r = t >> 1, cc = (t & 1) << 5;
    uint32_t* ch32 = (uint32_t*)Ch;
    uint32_t* cl32 = (uint32_t*)Cl;
#pragma unroll
    for (int q = 0; q < 8; q++) {
        float4 v = *(float4*)(scratch + r * 64 + cc + q * 4);
        float4 bb = *(const float4*)(bias + col0 + cc + q * 4);
        v.x += bb.x; v.y += bb.y; v.z += bb.z; v.w += bb.w;
        uint32_t h01 = bf16x2_of(v.y, v.x);
        uint32_t h23 = bf16x2_of(v.w, v.z);
        uint32_t l01 = bf16x2_of(v.y - bf16hi_f(h01), v.x - bf16lo_f(h01));
        uint32_t l23 = bf16x2_of(v.w - bf16hi_f(h23), v.z - bf16lo_f(h23));
        int o = (row0 + r) * (N >> 1) + ((col0 + cc) >> 1) + q * 2;
        ch32[o] = h01; ch32[o + 1] = h23;
        cl32[o] = l01; cl32[o + 1] = l23;
    }
}

// ============================================================================
// qkv GEMM: 3-stage pipelined, single sync per k-tile. Block 128x64.
// ============================================================================
#define GBF_SMEM 92160

__global__ __launch_bounds__(256) void bfgemm_bf(const __nv_bfloat16* __restrict__ Ah,
                                                 const __nv_bfloat16* __restrict__ Al,
                                                 const __nv_bfloat16* __restrict__ Bh,
                                                 const __nv_bfloat16* __restrict__ Bl,
                                                 const float* __restrict__ bias,
                                                 float* __restrict__ C, int ldc, int K,
                                                 int qcolsplit, int qrowblk) {
    extern __shared__ __align__(16) char sm[];
    const int col0 = blockIdx.x << 6;
    if (col0 < qcolsplit && (int)blockIdx.y >= qrowblk) return;
    const uint32_t smb = smem_u32(sm);
    const int t = threadIdx.x;
    const int w = t >> 5;
    const int row0 = blockIdx.y << 7;
    const int m0 = (w >> 1) << 5, n0 = (w & 1) << 5;
    const int KT = K >> 5;

    auto issue = [&](int kt, int stg) {
        int k0 = kt << 5;
        uint32_t sb = smb + (uint32_t)stg * 30720;
#pragma unroll
        for (int i = 0; i < 2; i++) {
            int id = t + (i << 8);
            int r = id >> 2, k8 = (id & 3) << 3;
            uint32_t so = (uint32_t)(r * 40 + k8) << 1;
            cpa16(sb + so,         Ah + (size_t)(row0 + r) * K + k0 + k8);
            cpa16(sb + 10240 + so, Al + (size_t)(row0 + r) * K + k0 + k8);
        }
        {
            int r = t >> 2, k8 = (t & 3) << 3;
            uint32_t so = (uint32_t)(r * 40 + k8) << 1;
            cpa16(sb + 20480 + so, Bh + (size_t)(col0 + r) * K + k0 + k8);
            cpa16(sb + 25600 + so, Bl + (size_t)(col0 + r) * K + k0 + k8);
        }
        cp_commit();
    };

    wmma::fragment<wmma::accumulator, 16, 16, 16, float> acc[2][2];
#pragma unroll
    for (int mi = 0; mi < 2; mi++)
#pragma unroll
        for (int ni = 0; ni < 2; ni++)
            wmma::fill_fragment(acc[mi][ni], 0.f);

    issue(0, 0);
    issue(1, 1);
    for (int kt = 0; kt < KT; kt++) {
        if (kt + 1 < KT) cp_wait1(); else cp_wait0();
        __syncthreads();
        if (kt + 2 < KT) issue(kt + 2, (kt + 2) % 3);
        char* sb = sm + (kt % 3) * 30720;
        __nv_bfloat16* sAh = (__nv_bfloat16*)sb;
        __nv_bfloat16* sAl = (__nv_bfloat16*)(sb + 10240);
        __nv_bfloat16* sBh = (__nv_bfloat16*)(sb + 20480);
        __nv_bfloat16* sBl = (__nv_bfloat16*)(sb + 25600);
#pragma unroll
        for (int ks = 0; ks < 2; ks++) {
            wmma::fragment<wmma::matrix_a, 16, 16, 16, __nv_bfloat16, wmma::row_major> ah0, ah1, al0, al1;
            wmma::fragment<wmma::matrix_b, 16, 16, 16, __nv_bfloat16, wmma::col_major> bh0, bh1, bl0, bl1;
            wmma::load_matrix_sync(ah0, sAh + (size_t)m0 * 40 + ks * 16, 40);
            wmma::load_matrix_sync(ah1, sAh + (size_t)(m0 + 16) * 40 + ks * 16, 40);
            wmma::load_matrix_sync(al0, sAl + (size_t)m0 * 40 + ks * 16, 40);
            wmma::load_matrix_sync(al1, sAl + (size_t)(m0 + 16) * 40 + ks * 16, 40);
            wmma::load_matrix_sync(bh0, sBh + (size_t)n0 * 40 + ks * 16, 40);
            wmma::load_matrix_sync(bh1, sBh + (size_t)(n0 + 16) * 40 + ks * 16, 40);
            wmma::load_matrix_sync(bl0, sBl + (size_t)n0 * 40 + ks * 16, 40);
            wmma::load_matrix_sync(bl1, sBl + (size_t)(n0 + 16) * 40 + ks * 16, 40);

            wmma::mma_sync(acc[0][0], ah0, bh0, acc[0][0]);
            wmma::mma_sync(acc[0][1], ah0, bh1, acc[0][1]);
            wmma::mma_sync(acc[1][0], ah1, bh0, acc[1][0]);
            wmma::mma_sync(acc[1][1], ah1, bh1, acc[1][1]);
            wmma::mma_sync(acc[0][0], ah0, bl0, acc[0][0]);
            wmma::mma_sync(acc[0][1], ah0, bl1, acc[0][1]);
            wmma::mma_sync(acc[1][0], ah1, bl0, acc[1][0]);
            wmma::mma_sync(acc[1][1], ah1, bl1, acc[1][1]);
            wmma::mma_sync(acc[0][0], al0, bh0, acc[0][0]);
            wmma::mma_sync(acc[0][1], al0, bh1, acc[0][1]);
            wmma::mma_sync(acc[1][0], al1, bh0, acc[1][0]);
            wmma::mma_sync(acc[1][1], al1, bh1, acc[1][1]);
        }
    }
    __syncthreads();

    float* scratch = (float*)sm;
#pragma unroll
    for (int mi = 0; mi < 2; mi++)
#pragma unroll
        for (int ni = 0; ni < 2; ni++)
            wmma::store_matrix_sync(scratch + (size_t)(m0 + mi * 16) * 64 + n0 + ni * 16,
                                    acc[mi][ni], 64, wmma::mem_row_major);
    __syncthreads();

    int r = t >> 1, cc = (t & 1) << 5;
#pragma unroll
    for (int q = 0; q < 8; q++) {
        float4 v = *(float4*)(scratch + r * 64 + cc + q * 4);
        float4 bb = *(const float4*)(bias + col0 + cc + q * 4);
        v.x += bb.x; v.y += bb.y; v.z += bb.z; v.w += bb.w;
        *(float4*)(C + (size_t)(row0 + r) * ldc + col0 + cc + q * 4) = v;
    }
}

// ============================================================================
// conv_out: 3-stage pipelined with transposed NCHW store.
// ============================================================================
#define GTR_SMEM 92160

__global__ __launch_bounds__(256) void bfgemm_tr_bf(const __nv_bfloat16* __restrict__ Ah,
                                                    const __nv_bfloat16* __restrict__ Al,
                                                    const __nv_bfloat16* __restrict__ Bh,
                                                    const __nv_bfloat16* __restrict__ Bl,
                                                    const float* __restrict__ bias,
                                                    float* __restrict__ out, int K) {
    extern __shared__ __align__(16) char sm[];
    const uint32_t smb = smem_u32(sm);
    const int t = threadIdx.x;
    const int w = t >> 5;
    const int row0 = blockIdx.y << 7, col0 = blockIdx.x << 6;
    const int b2 = row0 >> 12, hw0 = row0 & 4095;
    const int m0 = (w >> 1) << 5, n0 = (w & 1) << 5;
    const int KT = K >> 5;

    auto issue = [&](int kt, int stg) {
        int k0 = kt << 5;
        uint32_t sb = smb + (uint32_t)stg * 30720;
#pragma unroll
        for (int i = 0; i < 2; i++) {
            int id = t + (i << 8);
            int r = id >> 2, k8 = (id & 3) << 3;
            uint32_t so = (uint32_t)(r * 40 + k8) << 1;
            cpa16(sb + so,         Ah + (size_t)(row0 + r) * K + k0 + k8);
            cpa16(sb + 10240 + so, Al + (size_t)(row0 + r) * K + k0 + k8);
        }
        {
            int r = t >> 2, k8 = (t & 3) << 3;
            uint32_t so = (uint32_t)(r * 40 + k8) << 1;
            cpa16(sb + 20480 + so, Bh + (size_t)(col0 + r) * K + k0 + k8);
            cpa16(sb + 25600 + so, Bl + (size_t)(col0 + r) * K + k0 + k8);
        }
        cp_commit();
    };

    wmma::fragment<wmma::accumulator, 16, 16, 16, float> acc[2][2];
#pragma unroll
    for (int mi = 0; mi < 2; mi++)
#pragma unroll
        for (int ni = 0; ni < 2; ni++)
            wmma::fill_fragment(acc[mi][ni], 0.f);

    issue(0, 0);
    issue(1, 1);
    for (int kt = 0; kt < KT; kt++) {
        if (kt + 1 < KT) cp_wait1(); else cp_wait0();
        __syncthreads();
        if (kt + 2 < KT) issue(kt + 2, (kt + 2) % 3);
        char* sb = sm + (kt % 3) * 30720;
        __nv_bfloat16* sAh = (__nv_bfloat16*)sb;
        __nv_bfloat16* sAl = (__nv_bfloat16*)(sb + 10240);
        __nv_bfloat16* sBh = (__nv_bfloat16*)(sb + 20480);
        __nv_bfloat16* sBl = (__nv_bfloat16*)(sb + 25600);
#pragma unroll
        for (int ks = 0; ks < 2; ks++) {
            wmma::fragment<wmma::matrix_a, 16, 16, 16, __nv_bfloat16, wmma::row_major> ah0, ah1, al0, al1;
            wmma::fragment<wmma::matrix_b, 16, 16, 16, __nv_bfloat16, wmma::col_major> bh0, bh1, bl0, bl1;
            wmma::load_matrix_sync(ah0, sAh + (size_t)m0 * 40 + ks * 16, 40);
            wmma::load_matrix_sync(ah1, sAh + (size_t)(m0 + 16) * 40 + ks * 16, 40);
            wmma::load_matrix_sync(al0, sAl + (size_t)m0 * 40 + ks * 16, 40);
            wmma::load_matrix_sync(al1, sAl + (size_t)(m0 + 16) * 40 + ks * 16, 40);
            wmma::load_matrix_sync(bh0, sBh + (size_t)n0 * 40 + ks * 16, 40);
            wmma::load_matrix_sync(bh1, sBh + (size_t)(n0 + 16) * 40 + ks * 16, 40);
            wmma::load_matrix_sync(bl0, sBl + (size_t)n0 * 40 + ks * 16, 40);
            wmma::load_matrix_sync(bl1, sBl + (size_t)(n0 + 16) * 40 + ks * 16, 40);

            wmma::mma_sync(acc[0][0], ah0, bh0, acc[0][0]);
            wmma::mma_sync(acc[0][1], ah0, bh1, acc[0][1]);
            wmma::mma_sync(acc[1][0], ah1, bh0, acc[1][0]);
            wmma::mma_sync(acc[1][1], ah1, bh1, acc[1][1]);
            wmma::mma_sync(acc[0][0], ah0, bl0, acc[0][0]);
            wmma::mma_sync(acc[0][1], ah0, bl1, acc[0][1]);
            wmma::mma_sync(acc[1][0], ah1, bl0, acc[1][0]);
            wmma::mma_sync(acc[1][1], ah1, bl1, acc[1][1]);
            wmma::mma_sync(acc[0][0], al0, bh0, acc[0][0]);
            wmma::mma_sync(acc[0][1], al0, bh1, acc[0][1]);
            wmma::mma_sync(acc[1][0], al1, bh0, acc[1][0]);
            wmma::mma_sync(acc[1][1], al1, bh1, acc[1][1]);
        }
    }
    __syncthreads();

    float* scratch = (float*)sm;
#pragma unroll
    for (int mi = 0; mi < 2; mi++)
#pragma unroll
        for (int ni = 0; ni < 2; ni++)
            wmma::store_matrix_sync(scratch + (size_t)(n0 + ni * 16) * 132 + m0 + mi * 16,
                                    acc[mi][ni], 132, wmma::mem_col_major);
    __syncthreads();

    const int lane = t & 31;
#pragma unroll
    for (int nn = 0; nn < 8; nn++) {
        int n = (w << 3) + nn;
        float bv = bias[col0 + n];
        float* orow = out + (size_t)b2 * 1048576 + (size_t)(col0 + n) * 4096 + hw0;
#pragma unroll
        for (int it = 0; it < 4; it++) {
            int m = (it << 5) + lane;
            orow[m] = scratch[n * 132 + m] + bv;
        }
    }
}

// ============================================================================
// Windowed attention, 4-way key-split (R8/R9 version)
// ============================================================================
#define ATTN_SMEM 52224

__global__ __launch_bounds__(256) void attn_kernel(const float* __restrict__ qkv,
                                                   __nv_bfloat16* __restrict__ Oh,
                                                   __nv_bfloat16* __restrict__ Ol) {
    extern __shared__ __align__(16) char asmem[];
    float4 (*sK)[4] = (float4(*)[4])asmem;
    float4 (*sV)[4] = (float4(*)[4])(asmem + 16384);
    float* pm = (float*)(asmem + 32768);
    float* pl = (float*)(asmem + 33792);
    float* po = (float*)(asmem + 34816);

    const int h = blockIdx.x, w = blockIdx.y;
    const int t = threadIdx.x;
    const int sg = t >> 6, q = t & 63;
    const int T = g_win_cnt[w];
    const int* wt = &g_win_tok[w * CAP];

    for (int j = t; j < T; j += 256) {
        int tok = wt[j];
        const float4* kp = (const float4*)(qkv + (size_t)tok * 384 + 128 + h * 16);
        const float4* vp = (const float4*)(qkv + (size_t)tok * 384 + 256 + h * 16);
        sK[j][0] = kp[0]; sK[j][1] = kp[1]; sK[j][2] = kp[2]; sK[j][3] = kp[3];
        sV[j][0] = vp[0]; sV[j][1] = vp[1]; sV[j][2] = vp[2]; sV[j][3] = vp[3];
    }
    __syncthreads();

    const int qtok = wt[q];
    const float4* qp = (const float4*)(qkv + (size_t)qtok * 384 + h * 16);
    float4 q0 = qp[0], q1 = qp[1], q2 = qp[2], q3 = qp[3];

    const int j0 = (T * sg) >> 2, j1 = (T * (sg + 1)) >> 2;
    float m = -1e30f, l = 0.f;
    float4 o0 = {0,0,0,0}, o1 = {0,0,0,0}, o2 = {0,0,0,0}, o3 = {0,0,0,0};
    for (int j = j0; j < j1; j++) {
        float4 k0 = sK[j][0], k1 = sK[j][1], k2 = sK[j][2], k3 = sK[j][3];
        float s = q0.x*k0.x + q0.y*k0.y + q0.z*k0.z + q0.w*k0.w
                + q1.x*k1.x + q1.y*k1.y + q1.z*k1.z + q1.w*k1.w
                + q2.x*k2.x + q2.y*k2.y + q2.z*k2.z + q2.w*k2.w
                + q3.x*k3.x + q3.y*k3.y + q3.z*k3.z + q3.w*k3.w;
        s *= 0.25f;
        float mn = fmaxf(m, s);
        float sc = __expf(m - mn);
        float p  = __expf(s - mn);
        l = l * sc + p;
        float4 v0 = sV[j][0], v1 = sV[j][1], v2 = sV[j][2], v3 = sV[j][3];
        o0.x = o0.x*sc + p*v0.x; o0.y = o0.y*sc + p*v0.y; o0.z = o0.z*sc + p*v0.z; o0.w = o0.w*sc + p*v0.w;
        o1.x = o1.x*sc + p*v1.x; o1.y = o1.y*sc + p*v1.y; o1.z = o1.z*sc + p*v1.z; o1.w = o1.w*sc + p*v1.w;
        o2.x = o2.x*sc + p*v2.x; o2.y = o2.y*sc + p*v2.y; o2.z = o2.z*sc + p*v2.z; o2.w = o2.w*sc + p*v2.w;
        o3.x = o3.x*sc + p*v3.x; o3.y = o3.y*sc + p*v3.y; o3.z = o3.z*sc + p*v3.z; o3.w = o3.w*sc + p*v3.w;
        m = mn;
    }
    pm[t] = m;
    pl[t] = l;
    float* pop = po + (sg * 64 + q) * 17;
    pop[0] = o0.x; pop[1] = o0.y; pop[2]  = o0.z; pop[3]  = o0.w;
    pop[4] = o1.x; pop[5] = o1.y; pop[6]  = o1.z; pop[7]  = o1.w;
    pop[8] = o2.x; pop[9] = o2.y; pop[10] = o2.z; pop[11] = o2.w;
    pop[12] = o3.x; pop[13] = o3.y; pop[14] = o3.z; pop[15] = o3.w;
    __syncthreads();

    if (t < 64) {
        float m0 = pm[q], m1 = pm[64 + q], m2 = pm[128 + q], m3 = pm[192 + q];
        float mm = fmaxf(fmaxf(m0, m1), fmaxf(m2, m3));
        float e0 = __expf(m0 - mm), e1 = __expf(m1 - mm);
        float e2 = __expf(m2 - mm), e3 = __expf(m3 - mm);
        float lt = pl[q] * e0 + pl[64 + q] * e1 + pl[128 + q] * e2 + pl[192 + q] * e3;
        float inv = 1.f / lt;
        const float* p0 = po + q * 17;
        const float* p1 = po + (64 + q) * 17;
        const float* p2 = po + (128 + q) * 17;
        const float* p3 = po + (192 + q) * 17;
        uint32_t* oh32 = (uint32_t*)Oh;
        uint32_t* ol32 = (uint32_t*)Ol;
        int ob = qtok * 64 + h * 8;
#pragma unroll
        for (int j = 0; j < 8; j++) {
            float vlo = (p0[2*j]   * e0 + p1[2*j]   * e1 + p2[2*j]   * e2 + p3[2*j]   * e3) * inv;
            float vhi = (p0[2*j+1] * e0 + p1[2*j+1] * e1 + p2[2*j+1] * e2 + p3[2*j+1] * e3) * inv;
            uint32_t hh = bf16x2_of(vhi, vlo);
            oh32[ob + j] = hh;
            ol32[ob + j] = bf16x2_of(vhi - bf16hi_f(hh), vlo - bf16lo_f(hh));
        }
    }
}

// ============================================================================
// Fused proj + RK4 ODE on raw mma.sync (R9 version, unchanged)
// ============================================================================
#define ODE_SMEM 174592

__global__ __launch_bounds__(256, 1) void ode_mma(const __nv_bfloat16* __restrict__ Oh,
                                                  const __nv_bfloat16* __restrict__ Ol,
                                                  const __nv_bfloat16* __restrict__ PWh,
                                                  const __nv_bfloat16* __restrict__ PWl,
                                                  const float* __restrict__ pbias,
                                                  const __nv_bfloat16* __restrict__ Wh_g,
                                                  const __nv_bfloat16* __restrict__ Wl_g,
                                                  const float* __restrict__ bias,
                                                  __nv_bfloat16* __restrict__ Rh,
                                                  __nv_bfloat16* __restrict__ Rl) {
    extern __shared__ __align__(16) char sm[];
    float* sBias = (float*)sm;
    char* sWh  = sm + 512;
    char* sWl  = sm + 35328;
    char* sZh  = sm + 70144;
    char* sZl  = sm + 87552;
    char* sPWh = sm + 104960;
    char* sPWl = sm + 139776;
    float* sImg = (float*)(sm + 104960);

    const int t = threadIdx.x;
    const int lane = t & 31;
    const int wid = t >> 5;
    const int wm = wid >> 2, wn = wid & 3;
    const int m0 = wm << 5, n0 = wn << 5;
    const int row0 = blockIdx.x << 6;

    {
        const uint32_t* wh32 = (const uint32_t*)Wh_g;
        const uint32_t* wl32 = (const uint32_t*)Wl_g;
        const uint32_t* ph32 = (const uint32_t*)PWh;
        const uint32_t* pl32 = (const uint32_t*)PWl;
        uint32_t* dWh = (uint32_t*)sWh;
        uint32_t* dWl = (uint32_t*)sWl;
        uint32_t* dPh = (uint32_t*)sPWh;
        uint32_t* dPl = (uint32_t*)sPWl;
        for (int idx = t; idx < 8192; idx += 256) {
            int n = idx >> 6, c2 = idx & 63;
            dWh[n * 68 + c2] = wh32[idx];
            dWl[n * 68 + c2] = wl32[idx];
            dPh[n * 68 + c2] = ph32[idx];
            dPl[n * 68 + c2] = pl32[idx];
        }
        const uint32_t* oh32 = (const uint32_t*)Oh + (size_t)row0 * 64;
        const uint32_t* ol32 = (const uint32_t*)Ol + (size_t)row0 * 64;
        uint32_t* zh = (uint32_t*)sZh;
        uint32_t* zl = (uint32_t*)sZl;
        for (int idx = t; idx < 4096; idx += 256) {
            int n = idx >> 6, c2 = idx & 63;
            zh[n * 68 + c2] = oh32[idx];
            zl[n * 68 + c2] = ol32[idx];
        }
        if (t < 128) sBias[t] = bias[t];
    }
    __syncthreads();

    const int g3 = lane >> 3, r8 = lane & 7;
    uint32_t aOff[2], bOff[2];
#pragma unroll
    for (int mf = 0; mf < 2; mf++)
        aOff[mf] = (uint32_t)((m0 + mf * 16 + (g3 & 1) * 8 + r8) * 136) * 2 + (g3 >> 1) * 16;
#pragma unroll
    for (int nt = 0; nt < 2; nt++)
        bOff[nt] = (uint32_t)((n0 + nt * 16 + (g3 >> 1) * 8 + r8) * 136) * 2 + (g3 & 1) * 16;

    const uint32_t zhB = smem_u32(sZh), zlB = smem_u32(sZl);
    const uint32_t whB = smem_u32(sWh), wlB = smem_u32(sWl);
    const uint32_t phB = smem_u32(sPWh), plB = smem_u32(sPWl);

    const int gr = lane >> 2, q2 = (lane & 3) << 1;
    float bias2[4][2];
#pragma unroll
    for (int nj = 0; nj < 4; nj++) {
        bias2[nj][0] = sBias[n0 + nj * 8 + q2];
        bias2[nj][1] = sBias[n0 + nj * 8 + q2 + 1];
    }

    float d[2][4][4], y[2][4][4], accv[2][4][4];

#define MMA_PHASE(AH, AL, BH, BL)                                                  \
    _Pragma("unroll")                                                              \
    for (int kk = 0; kk < 8; kk++) {                                               \
        uint32_t ko = kk * 32;                                                     \
        uint32_t ah0[4], ah1[4], al0[4], al1[4];                                   \
        uint32_t bh0[4], bh1[4], bl0[4], bl1[4];                                   \
        ldm4(ah0, (AH) + aOff[0] + ko); ldm4(ah1, (AH) + aOff[1] + ko);            \
        ldm4(al0, (AL) + aOff[0] + ko); ldm4(al1, (AL) + aOff[1] + ko);            \
        ldm4(bh0, (BH) + bOff[0] + ko); ldm4(bh1, (BH) + bOff[1] + ko);            \
        ldm4(bl0, (BL) + bOff[0] + ko); ldm4(bl1, (BL) + bOff[1] + ko);            \
        _Pragma("unroll")                                                          \
        for (int nj = 0; nj < 4; nj++) {                                           \
            const uint32_t* bhp = (nj < 2) ? bh0 : bh1;                            \
            const uint32_t* blp = (nj < 2) ? bl0 : bl1;                            \
            uint32_t bh_0 = bhp[(nj & 1) * 2], bh_1 = bhp[(nj & 1) * 2 + 1];       \
            uint32_t bl_0 = blp[(nj & 1) * 2], bl_1 = blp[(nj & 1) * 2 + 1];       \
            mma16816(d[0][nj], ah0, bh_0, bh_1);                                   \
            mma16816(d[1][nj], ah1, bh_0, bh_1);                                   \
            mma16816(d[0][nj], al0, bh_0, bh_1);                                   \
            mma16816(d[1][nj], al1, bh_0, bh_1);                                   \
            mma16816(d[0][nj], ah0, bl_0, bl_1);                                   \
            mma16816(d[1][nj], ah1, bl_0, bl_1);                                   \
        }                                                                          \
    }

#pragma unroll
    for (int mf = 0; mf < 2; mf++)
#pragma unroll
        for (int nj = 0; nj < 4; nj++)
#pragma unroll
            for (int i = 0; i < 4; i++) d[mf][nj][i] = 0.f;
    MMA_PHASE(zhB, zlB, phB, plB)
    __syncthreads();

#pragma unroll
    for (int mf = 0; mf < 2; mf++) {
#pragma unroll
        for (int nj = 0; nj < 4; nj++) {
            const int c = n0 + nj * 8 + q2;
            float pb0 = pbias[c], pb1 = pbias[c + 1];
#pragma unroll
            for (int hh = 0; hh < 2; hh++) {
                const int row = m0 + mf * 16 + gr + hh * 8;
                float z0 = d[mf][nj][hh * 2]     + pb0;
                float z1 = d[mf][nj][hh * 2 + 1] + pb1;
                y[mf][nj][hh * 2] = z0; y[mf][nj][hh * 2 + 1] = z1;
                *(float2*)(sImg + row * 128 + c) = make_float2(z0, z1);
                uint32_t hz = bf16x2_of(z1, z0);
                *(uint32_t*)(sZh + (row * 136 + c) * 2) = hz;
                *(uint32_t*)(sZl + (row * 136 + c) * 2) =
                    bf16x2_of(z1 - bf16hi_f(hz), z0 - bf16lo_f(hz));
            }
        }
    }
    __syncthreads();

    for (int ev = 0; ev < 16; ev++) {
#pragma unroll
        for (int mf = 0; mf < 2; mf++)
#pragma unroll
            for (int nj = 0; nj < 4; nj++)
#pragma unroll
                for (int i = 0; i < 4; i++) d[mf][nj][i] = 0.f;
        MMA_PHASE(zhB, zlB, whB, wlB)
        __syncthreads();

        const int st = ev & 3;
        const float zc = (st < 2) ? 0.125f : 0.25f;
        const float aw = (st == 1 || st == 2) ? 2.f : 1.f;
#pragma unroll
        for (int mf = 0; mf < 2; mf++) {
#pragma unroll
            for (int nj = 0; nj < 4; nj++) {
                const int c = n0 + nj * 8 + q2;
#pragma unroll
                for (int hh = 0; hh < 2; hh++) {
                    const int row = m0 + mf * 16 + gr + hh * 8;
                    float kf0 = fmaxf(d[mf][nj][hh * 2]     + bias2[nj][0], 0.f);
                    float kf1 = fmaxf(d[mf][nj][hh * 2 + 1] + bias2[nj][1], 0.f);
                    float a0 = (st == 0) ? kf0 : accv[mf][nj][hh * 2]     + aw * kf0;
                    float a1 = (st == 0) ? kf1 : accv[mf][nj][hh * 2 + 1] + aw * kf1;
                    accv[mf][nj][hh * 2] = a0; accv[mf][nj][hh * 2 + 1] = a1;
                    float z0, z1;
                    if (st < 3) {
                        z0 = y[mf][nj][hh * 2]     + zc * kf0;
                        z1 = y[mf][nj][hh * 2 + 1] + zc * kf1;
                    } else {
                        y[mf][nj][hh * 2]     += (1.f / 24.f) * a0;
                        y[mf][nj][hh * 2 + 1] += (1.f / 24.f) * a1;
                        z0 = y[mf][nj][hh * 2]; z1 = y[mf][nj][hh * 2 + 1];
                    }
                    uint32_t hz = bf16x2_of(z1, z0);
                    *(uint32_t*)(sZh + (row * 136 + c) * 2) = hz;
                    *(uint32_t*)(sZl + (row * 136 + c) * 2) =
                        bf16x2_of(z1 - bf16hi_f(hz), z0 - bf16lo_f(hz));
                }
            }
        }
        __syncthreads();
    }

    uint32_t* rh32 = (uint32_t*)Rh;
    uint32_t* rl32 = (uint32_t*)Rl;
#pragma unroll
    for (int mf = 0; mf < 2; mf++) {
#pragma unroll
        for (int nj = 0; nj < 4; nj++) {
            const int c = n0 + nj * 8 + q2;
#pragma unroll
            for (int hh = 0; hh < 2; hh++) {
                const int row = m0 + mf * 16 + gr + hh * 8;
                float2 iv = *(const float2*)(sImg + row * 128 + c);
                float r0 = y[mf][nj][hh * 2]     + iv.x;
                float r1 = y[mf][nj][hh * 2 + 1] + iv.y;
                uint32_t hz = bf16x2_of(r1, r0);
                int o = (row0 + row) * 64 + (c >> 1);
                rh32[o] = hz;
                rl32[o] = bf16x2_of(r1 - bf16hi_f(hz), r0 - bf16lo_f(hz));
            }
        }
    }
#undef MMA_PHASE
}

// ---------------- launch ----------------
extern "C" void kernel_launch(void* const* d_in, const int* in_sizes, int n_in,
                              void* d_out, int out_size) {
    const float* img   = (const float*)d_in[0];
    const int*   ptsuv = (const int*)  d_in[1];
    const float* ptsf  = (const float*)d_in[2];
    const float* wci   = (const float*)d_in[3];
    const float* bci   = (const float*)d_in[4];
    const float* wqkv  = (const float*)d_in[5];
    const float* bqkv  = (const float*)d_in[6];
    const float* wpr   = (const float*)d_in[7];
    const float* bpr   = (const float*)d_in[8];
    const float* wode  = (const float*)d_in[9];
    const float* bode  = (const float*)d_in[10];
    const float* wco   = (const float*)d_in[11];
    const float* bco   = (const float*)d_in[12];
    float* out = (float*)d_out;

    float *pqkv;
    __nv_bfloat16 *pwh, *pwl, *pfh, *pfl, *poh, *pol, *prh, *prl, *pih, *pil;
    cudaGetSymbolAddress((void**)&pqkv, g_qkv);
    cudaGetSymbolAddress((void**)&pwh,  g_wh);
    cudaGetSymbolAddress((void**)&pwl,  g_wl);
    cudaGetSymbolAddress((void**)&pfh,  g_feath);
    cudaGetSymbolAddress((void**)&pfl,  g_featl);
    cudaGetSymbolAddress((void**)&poh,  g_oh);
    cudaGetSymbolAddress((void**)&pol,  g_ol);
    cudaGetSymbolAddress((void**)&prh,  g_resh);
    cudaGetSymbolAddress((void**)&prl,  g_resl);
    cudaGetSymbolAddress((void**)&pih,  g_imgh);
    cudaGetSymbolAddress((void**)&pil,  g_imgl);

    cudaFuncSetAttribute(ode_mma,      cudaFuncAttributeMaxDynamicSharedMemorySize, ODE_SMEM);
    cudaFuncSetAttribute(bfgemm_bf,    cudaFuncAttributeMaxDynamicSharedMemorySize, GBF_SMEM);
    cudaFuncSetAttribute(bfgemm_tr_bf, cudaFuncAttributeMaxDynamicSharedMemorySize, GTR_SMEM);
    cudaFuncSetAttribute(wgemm_ca3,    cudaFuncAttributeMaxDynamicSharedMemorySize, CA_SMEM);
    cudaFuncSetAttribute(attn_kernel,  cudaFuncAttributeMaxDynamicSharedMemorySize, ATTN_SMEM);

    prep<<<3680, 256>>>(wci, wqkv, wpr, wode, wco, ptsf, ptsuv, img);
    pt_scatter<<<NCHUNK, 256>>>();
    // conv_in: 3-stage pipelined from split NCHW image (M=8192,N=128,K=256)
    wgemm_ca3<<<dim3(2, 64), 256, CA_SMEM>>>(pih, pil, pwh + WOFF_CI, pwl + WOFF_CI,
                                             bci, pfh, pfl, 128, 256);
    // qkv: 3-stage; Q (cols<128) only for pixel rows (by<64)
    bfgemm_bf<<<dim3(6, 128), 256, GBF_SMEM>>>(pfh, pfl, pwh + WOFF_QKV, pwl + WOFF_QKV,
                                               bqkv, pqkv, 384, 128, 128, 64);
    // attention (4-way key split) -> o h/l
    attn_kernel<<<dim3(8, 128), 256, ATTN_SMEM>>>(pqkv, poh, pol);
    // fused proj + RK4 ODE on mma.sync -> res h/l
    ode_mma<<<128, 256, ODE_SMEM>>>(poh, pol, pwh + WOFF_PR, pwl + WOFF_PR, bpr,
                                    pwh + WOFF_ODE, pwl + WOFF_ODE, bode, prh, prl);
    // conv_out: 3-stage -> NCHW out  (FIX: N=256 needs 4 column blocks)
    bfgemm_tr_bf<<<dim3(4, 64), 256, GTR_SMEM>>>(prh, prl, pwh + WOFF_CO, pwl + WOFF_CO,
                                                 bco, out, 128);
}